// round 1
// baseline (speedup 1.0000x reference)
#include <cuda_runtime.h>
#include <math.h>

#define NROIS 4096
#define NBANK 8192
#define DIMIN 2048
#define QDIM_ 2048
#define LAT 1024

// ---------------- scratch (device globals: allocation-free) ----------------
__device__ float g_q1[NROIS * LAT];
__device__ float g_q2[NROIS * LAT];
__device__ float g_k1[NBANK * LAT];
__device__ float g_v1[NBANK * LAT];
__device__ float g_k2[NBANK * LAT];
__device__ float g_v2[NBANK * LAT];
__device__ float g_p [(long)NROIS * NBANK];   // scores / probs, reused per branch
__device__ float g_f1[NROIS * LAT];
__device__ float g_f2[NROIS * LAT];
__device__ float g_x [NROIS * LAT];

// ---------------- generic fp32 SGEMM ----------------
// C[m][n] = alpha * sum_k A[m][k] * Bval + (BIAS ? bias[n] : 0)
//   TRANSB=true : Bval = B[n][k]   (B is [N,K] row-major; torch Linear weight)
//   TRANSB=false: Bval = B[k][n]   (B is [K,N] row-major; P@V case)
// BM=BN=128, BK=8, 256 threads, 8x8 per-thread tile. All dims divisible.
template <bool TRANSB, bool BIAS>
__global__ __launch_bounds__(256) void sgemm_kernel(
    const float* __restrict__ A, const float* __restrict__ B,
    const float* __restrict__ bias, float* __restrict__ C,
    int M, int N, int K, float alpha)
{
    const int BK = 8;
    __shared__ float As[BK][128];
    __shared__ float Bs[BK][128];

    const int tid = threadIdx.x;
    const int tx = tid & 15;   // 0..15  (n direction)
    const int ty = tid >> 4;   // 0..15  (m direction)

    const long cRow = (long)blockIdx.y * 128;
    const long cCol = (long)blockIdx.x * 128;

    // A tile load: 128 rows x 8 cols, one float4 per thread
    const int arow = tid >> 1;         // 0..127
    const int acol = (tid & 1) * 4;    // 0 or 4
    // B tile load (!TRANSB): 8 rows x 128 cols, one float4 per thread
    const int brow = tid >> 5;         // 0..7
    const int bcol = (tid & 31) * 4;   // 0..124

    const float* Aptr = A + (cRow + arow) * (long)K + acol;
    const float* Bptr;
    if (TRANSB) Bptr = B + (cCol + arow) * (long)K + acol;
    else        Bptr = B + (long)brow * N + cCol + bcol;

    float acc[8][8];
#pragma unroll
    for (int i = 0; i < 8; i++)
#pragma unroll
        for (int j = 0; j < 8; j++) acc[i][j] = 0.f;

    for (int k0 = 0; k0 < K; k0 += BK) {
        float4 a4 = *(const float4*)Aptr;  Aptr += BK;
        As[acol + 0][arow] = a4.x;
        As[acol + 1][arow] = a4.y;
        As[acol + 2][arow] = a4.z;
        As[acol + 3][arow] = a4.w;
        if (TRANSB) {
            float4 b4 = *(const float4*)Bptr;  Bptr += BK;
            Bs[acol + 0][arow] = b4.x;
            Bs[acol + 1][arow] = b4.y;
            Bs[acol + 2][arow] = b4.z;
            Bs[acol + 3][arow] = b4.w;
        } else {
            float4 b4 = *(const float4*)Bptr;  Bptr += (long)BK * N;
            *(float4*)&Bs[brow][bcol] = b4;
        }
        __syncthreads();
#pragma unroll
        for (int kk = 0; kk < BK; kk++) {
            float ar[8], br[8];
            *(float4*)&ar[0] = *(const float4*)&As[kk][ty * 8];
            *(float4*)&ar[4] = *(const float4*)&As[kk][ty * 8 + 4];
            *(float4*)&br[0] = *(const float4*)&Bs[kk][tx * 8];
            *(float4*)&br[4] = *(const float4*)&Bs[kk][tx * 8 + 4];
#pragma unroll
            for (int i = 0; i < 8; i++)
#pragma unroll
                for (int j = 0; j < 8; j++)
                    acc[i][j] += ar[i] * br[j];
        }
        __syncthreads();
    }

#pragma unroll
    for (int i = 0; i < 8; i++) {
        const long row = cRow + ty * 8 + i;
#pragma unroll
        for (int j4 = 0; j4 < 2; j4++) {
            const int j = j4 * 4;
            const long col = cCol + tx * 8 + j;
            float4 o;
            o.x = alpha * acc[i][j + 0];
            o.y = alpha * acc[i][j + 1];
            o.z = alpha * acc[i][j + 2];
            o.w = alpha * acc[i][j + 3];
            if (BIAS) {
                o.x += bias[col + 0];
                o.y += bias[col + 1];
                o.z += bias[col + 2];
                o.w += bias[col + 3];
            }
            *(float4*)&C[row * (long)N + col] = o;
        }
    }
}

// ---------------- row softmax over NBANK=8192, in place ----------------
// one block of 256 threads per row; whole row held in registers (32 f / thread)
__global__ __launch_bounds__(256) void softmax_kernel(float* __restrict__ P)
{
    const int row = blockIdx.x;
    const int tid = threadIdx.x;
    float4* rowp = (float4*)(P + (long)row * NBANK);

    float4 v[8];
    float lmax = -3.0e38f;
#pragma unroll
    for (int j = 0; j < 8; j++) {
        v[j] = rowp[tid + j * 256];
        lmax = fmaxf(lmax, fmaxf(fmaxf(v[j].x, v[j].y), fmaxf(v[j].z, v[j].w)));
    }

    __shared__ float red[256];
    red[tid] = lmax;
    __syncthreads();
    for (int s = 128; s > 0; s >>= 1) {
        if (tid < s) red[tid] = fmaxf(red[tid], red[tid + s]);
        __syncthreads();
    }
    const float m = red[0];
    __syncthreads();

    float lsum = 0.f;
#pragma unroll
    for (int j = 0; j < 8; j++) {
        v[j].x = __expf(v[j].x - m);
        v[j].y = __expf(v[j].y - m);
        v[j].z = __expf(v[j].z - m);
        v[j].w = __expf(v[j].w - m);
        lsum += v[j].x + v[j].y + v[j].z + v[j].w;
    }
    red[tid] = lsum;
    __syncthreads();
    for (int s = 128; s > 0; s >>= 1) {
        if (tid < s) red[tid] += red[tid + s];
        __syncthreads();
    }
    const float inv = 1.f / red[0];

#pragma unroll
    for (int j = 0; j < 8; j++) {
        v[j].x *= inv; v[j].y *= inv; v[j].z *= inv; v[j].w *= inv;
        rowp[tid + j * 256] = v[j];
    }
}

// ---------------- cpair = f1*f2 ; LayerNorm ; PReLU ----------------
// one block of 256 threads per row of LAT=1024 (1 float4 per thread)
__global__ __launch_bounds__(256) void gate_ln_kernel(
    const float* __restrict__ f1, const float* __restrict__ f2,
    const float* __restrict__ lnw, const float* __restrict__ lnb,
    const float* __restrict__ prelu_a, float* __restrict__ x)
{
    const int row = blockIdx.x;
    const int tid = threadIdx.x;
    const float4 a = ((const float4*)(f1 + (long)row * LAT))[tid];
    const float4 b = ((const float4*)(f2 + (long)row * LAT))[tid];
    float4 c;
    c.x = a.x * b.x; c.y = a.y * b.y; c.z = a.z * b.z; c.w = a.w * b.w;

    __shared__ float red[256];
    // mean
    red[tid] = c.x + c.y + c.z + c.w;
    __syncthreads();
    for (int s = 128; s > 0; s >>= 1) {
        if (tid < s) red[tid] += red[tid + s];
        __syncthreads();
    }
    const float mu = red[0] * (1.f / LAT);
    __syncthreads();
    // centered variance (two-pass)
    float dx = c.x - mu, dy = c.y - mu, dz = c.z - mu, dw = c.w - mu;
    red[tid] = dx * dx + dy * dy + dz * dz + dw * dw;
    __syncthreads();
    for (int s = 128; s > 0; s >>= 1) {
        if (tid < s) red[tid] += red[tid + s];
        __syncthreads();
    }
    const float rstd = rsqrtf(red[0] * (1.f / LAT) + 1e-5f);
    const float slope = prelu_a[0];

    const float4 w = ((const float4*)lnw)[tid];
    const float4 bb = ((const float4*)lnb)[tid];
    float4 o;
    o.x = dx * rstd * w.x + bb.x;
    o.y = dy * rstd * w.y + bb.y;
    o.z = dz * rstd * w.z + bb.z;
    o.w = dw * rstd * w.w + bb.w;
    o.x = o.x >= 0.f ? o.x : slope * o.x;
    o.y = o.y >= 0.f ? o.y : slope * o.y;
    o.z = o.z >= 0.f ? o.z : slope * o.z;
    o.w = o.w >= 0.f ? o.w : slope * o.w;
    ((float4*)(x + (long)row * LAT))[tid] = o;
}

// ---------------- launch ----------------
extern "C" void kernel_launch(void* const* d_in, const int* in_sizes, int n_in,
                              void* d_out, int out_size)
{
    const float* feat = (const float*)d_in[0];
    const float* bank = (const float*)d_in[1];
    const float* Wc1 = (const float*)d_in[2];  const float* bc1 = (const float*)d_in[3];
    const float* Wc2 = (const float*)d_in[4];  const float* bc2 = (const float*)d_in[5];
    const float* Wc3 = (const float*)d_in[6];  const float* bc3 = (const float*)d_in[7];
    const float* Wd1 = (const float*)d_in[8];  const float* bd1 = (const float*)d_in[9];
    const float* Wd2 = (const float*)d_in[10]; const float* bd2 = (const float*)d_in[11];
    const float* Wd3 = (const float*)d_in[12]; const float* bd3 = (const float*)d_in[13];
    const float* lnw = (const float*)d_in[14]; const float* lnb = (const float*)d_in[15];
    const float* pra = (const float*)d_in[16];
    const float* Wffn = (const float*)d_in[17]; const float* bffn = (const float*)d_in[18];
    float* out = (float*)d_out;

    float *q1, *q2, *k1, *v1, *k2, *v2, *p, *f1, *f2, *x;
    cudaGetSymbolAddress((void**)&q1, g_q1);
    cudaGetSymbolAddress((void**)&q2, g_q2);
    cudaGetSymbolAddress((void**)&k1, g_k1);
    cudaGetSymbolAddress((void**)&v1, g_v1);
    cudaGetSymbolAddress((void**)&k2, g_k2);
    cudaGetSymbolAddress((void**)&v2, g_v2);
    cudaGetSymbolAddress((void**)&p,  g_p);
    cudaGetSymbolAddress((void**)&f1, g_f1);
    cudaGetSymbolAddress((void**)&f2, g_f2);
    cudaGetSymbolAddress((void**)&x,  g_x);

    const dim3 blk(256);
    const float inv_sqrt = 0.03125f;  // 1/sqrt(1024)

    // projections: X @ W^T + b
    sgemm_kernel<true, true><<<dim3(LAT / 128, NROIS / 128), blk>>>(feat, Wc1, bc1, q1, NROIS, LAT, QDIM_, 1.f);
    sgemm_kernel<true, true><<<dim3(LAT / 128, NROIS / 128), blk>>>(feat, Wd1, bd1, q2, NROIS, LAT, QDIM_, 1.f);
    sgemm_kernel<true, true><<<dim3(LAT / 128, NBANK / 128), blk>>>(bank, Wc2, bc2, k1, NBANK, LAT, DIMIN, 1.f);
    sgemm_kernel<true, true><<<dim3(LAT / 128, NBANK / 128), blk>>>(bank, Wc3, bc3, v1, NBANK, LAT, DIMIN, 1.f);
    sgemm_kernel<true, true><<<dim3(LAT / 128, NBANK / 128), blk>>>(bank, Wd2, bd2, k2, NBANK, LAT, DIMIN, 1.f);
    sgemm_kernel<true, true><<<dim3(LAT / 128, NBANK / 128), blk>>>(bank, Wd3, bd3, v2, NBANK, LAT, DIMIN, 1.f);

    // branch 1: scores -> softmax -> P @ V
    sgemm_kernel<true, false><<<dim3(NBANK / 128, NROIS / 128), blk>>>(q1, k1, nullptr, p, NROIS, NBANK, LAT, inv_sqrt);
    softmax_kernel<<<NROIS, blk>>>(p);
    sgemm_kernel<false, false><<<dim3(LAT / 128, NROIS / 128), blk>>>(p, v1, nullptr, f1, NROIS, LAT, NBANK, 1.f);

    // branch 2 (reuses score buffer; stream-ordered)
    sgemm_kernel<true, false><<<dim3(NBANK / 128, NROIS / 128), blk>>>(q2, k2, nullptr, p, NROIS, NBANK, LAT, inv_sqrt);
    softmax_kernel<<<NROIS, blk>>>(p);
    sgemm_kernel<false, false><<<dim3(LAT / 128, NROIS / 128), blk>>>(p, v2, nullptr, f2, NROIS, LAT, NBANK, 1.f);

    // gate + LayerNorm + PReLU
    gate_ln_kernel<<<NROIS, blk>>>(f1, f2, lnw, lnb, pra, x);

    // FFN: x @ Wffn^T + bffn -> out
    sgemm_kernel<true, true><<<dim3(DIMIN / 128, NROIS / 128), blk>>>(x, Wffn, bffn, out, NROIS, DIMIN, LAT, 1.f);
}

// round 3
// speedup vs baseline: 3.2625x; 3.2625x over previous
#include <cuda_runtime.h>
#include <cstdint>

#define NROIS 4096
#define NBANK 8192
#define DIMIN 2048
#define QDIM_ 2048
#define LAT 1024

// ---------------- scratch (device globals: allocation-free) ----------------
__device__ float g_rfeat[NROIS * QDIM_];
__device__ float g_rbank[NBANK * DIMIN];
__device__ float g_rw[7][LAT * DIMIN];   // Wc1,Wc2,Wc3,Wd1,Wd2,Wd3,Wffn
__device__ float g_q1[NROIS * LAT];
__device__ float g_q2[NROIS * LAT];
__device__ float g_k1[NBANK * LAT];
__device__ float g_k2[NBANK * LAT];
__device__ float g_v1t[LAT * NBANK];
__device__ float g_v2t[LAT * NBANK];
__device__ float g_p[(long)NROIS * NBANK];
__device__ float g_f1[NROIS * LAT];
__device__ float g_f2[NROIS * LAT];
__device__ float g_x[NROIS * LAT];

// ---------------- helpers ----------------
__device__ __forceinline__ uint32_t smem_u32(const void* p) {
    uint32_t r;
    asm("{ .reg .u64 t; cvta.to.shared.u64 t, %1; cvt.u32.u64 %0, t; }" : "=r"(r) : "l"(p));
    return r;
}
__device__ __forceinline__ float tf32r(float x) {
    uint32_t u;
    asm("cvt.rna.tf32.f32 %0, %1;" : "=r"(u) : "f"(x));
    return __uint_as_float(u);
}
__device__ __forceinline__ void cp16(const float* smem_dst, const float* gsrc) {
    uint32_t a = smem_u32(smem_dst);
    asm volatile("cp.async.cg.shared.global [%0], [%1], 16;" :: "r"(a), "l"(gsrc) : "memory");
}
__device__ __forceinline__ void mma_tf32(float* d, const uint32_t* a, const uint32_t* b) {
    asm volatile(
        "mma.sync.aligned.m16n8k8.row.col.f32.tf32.tf32.f32 "
        "{%0,%1,%2,%3}, {%4,%5,%6,%7}, {%8,%9}, {%0,%1,%2,%3};"
        : "+f"(d[0]), "+f"(d[1]), "+f"(d[2]), "+f"(d[3])
        : "r"(a[0]), "r"(a[1]), "r"(a[2]), "r"(a[3]), "r"(b[0]), "r"(b[1]));
}

// ---------------- tf32 mma.sync GEMM: C = alpha * A[M,K] * B[N,K]^T (+bias) ----
#define BM 128
#define BN 128
#define BK 32
#define STAGES 4
#define LDS_ 36                       // padded floats per smem row (conflict-free)
#define TILE_F (128 * LDS_)           // 4608 floats per operand tile
#define STAGE_F (2 * TILE_F)          // A + B per stage
#define GSMEM (STAGES * STAGE_F * 4)  // bytes

template <bool ROWBIAS, bool HASBIAS, bool ROUND_OUT>
__global__ __launch_bounds__(256, 1)
void gemm_mma(const float* __restrict__ A, const float* __restrict__ B,
              const float* __restrict__ bias, float* __restrict__ C,
              int M, int N, int K, float alpha)
{
    extern __shared__ float sm[];
    const int tid = threadIdx.x;
    const int lane = tid & 31;
    const int wid = tid >> 5;
    const int wm = (wid >> 2) * 64;   // warp M offset (2 warps in M)
    const int wn = (wid & 3) * 32;    // warp N offset (4 warps in N)
    const long cRow = (long)blockIdx.y * BM;
    const long cCol = (long)blockIdx.x * BN;
    const int iters = K / BK;

    const float* Abase = A + cRow * (long)K;
    const float* Bbase = B + cCol * (long)K;

    auto load_stage = [&](int j, int s) {
        const float* Ag = Abase + (long)j * BK;
        const float* Bg = Bbase + (long)j * BK;
        float* Ast = sm + s * STAGE_F;
        float* Bst = Ast + TILE_F;
#pragma unroll
        for (int n = 0; n < 4; n++) {
            int c = tid + n * 256;           // 0..1023
            int row = c >> 3, ci = c & 7;    // 128 rows x 8 16B-chunks
            cp16(Ast + row * LDS_ + ci * 4, Ag + (long)row * K + ci * 4);
        }
#pragma unroll
        for (int n = 0; n < 4; n++) {
            int c = tid + n * 256;
            int row = c >> 3, ci = c & 7;
            cp16(Bst + row * LDS_ + ci * 4, Bg + (long)row * K + ci * 4);
        }
        asm volatile("cp.async.commit_group;" ::: "memory");
    };

    float acc[4][4][4];
#pragma unroll
    for (int mi = 0; mi < 4; mi++)
#pragma unroll
        for (int ni = 0; ni < 4; ni++)
#pragma unroll
            for (int r = 0; r < 4; r++) acc[mi][ni][r] = 0.f;

#pragma unroll
    for (int j = 0; j < STAGES - 1; j++) load_stage(j, j);

    for (int i = 0; i < iters; i++) {
        asm volatile("cp.async.wait_group %0;" :: "n"(STAGES - 2) : "memory");
        __syncthreads();

        const int jn = i + STAGES - 1;
        if (jn < iters) load_stage(jn, jn % STAGES);

        const uint32_t* Au = (const uint32_t*)(sm + (i % STAGES) * STAGE_F);
        const uint32_t* Bu = Au + TILE_F;

#pragma unroll
        for (int ks = 0; ks < 4; ks++) {
            const int kq = ks * 8 + (lane & 3);
            uint32_t a[4][4];
#pragma unroll
            for (int mi = 0; mi < 4; mi++) {
                const int r0 = wm + mi * 16 + (lane >> 2);
                a[mi][0] = Au[r0 * LDS_ + kq];
                a[mi][1] = Au[(r0 + 8) * LDS_ + kq];
                a[mi][2] = Au[r0 * LDS_ + kq + 4];
                a[mi][3] = Au[(r0 + 8) * LDS_ + kq + 4];
            }
            uint32_t b[4][2];
#pragma unroll
            for (int ni = 0; ni < 4; ni++) {
                const int c0 = wn + ni * 8 + (lane >> 2);
                b[ni][0] = Bu[c0 * LDS_ + kq];
                b[ni][1] = Bu[c0 * LDS_ + kq + 4];
            }
#pragma unroll
            for (int mi = 0; mi < 4; mi++)
#pragma unroll
                for (int ni = 0; ni < 4; ni++)
                    mma_tf32(acc[mi][ni], a[mi], b[ni]);
        }
    }

    // epilogue: direct register -> gmem
#pragma unroll
    for (int mi = 0; mi < 4; mi++) {
        const long rg = cRow + wm + mi * 16 + (lane >> 2);
        float rb0 = 0.f, rb1 = 0.f;
        if (ROWBIAS && HASBIAS) { rb0 = __ldg(&bias[rg]); rb1 = __ldg(&bias[rg + 8]); }
#pragma unroll
        for (int ni = 0; ni < 4; ni++) {
            const long cg = cCol + wn + ni * 8 + (lane & 3) * 2;
            float v0 = alpha * acc[mi][ni][0];
            float v1 = alpha * acc[mi][ni][1];
            float v2 = alpha * acc[mi][ni][2];
            float v3 = alpha * acc[mi][ni][3];
            if (HASBIAS) {
                if (ROWBIAS) { v0 += rb0; v1 += rb0; v2 += rb1; v3 += rb1; }
                else {
                    float cb0 = __ldg(&bias[cg]), cb1 = __ldg(&bias[cg + 1]);
                    v0 += cb0; v1 += cb1; v2 += cb0; v3 += cb1;
                }
            }
            if (ROUND_OUT) { v0 = tf32r(v0); v1 = tf32r(v1); v2 = tf32r(v2); v3 = tf32r(v3); }
            float2 lo; lo.x = v0; lo.y = v1;
            float2 hi; hi.x = v2; hi.y = v3;
            *(float2*)&C[rg * (long)N + cg] = lo;
            *(float2*)&C[(rg + 8) * (long)N + cg] = hi;
        }
    }
}

// ---------------- tf32 pre-round (elementwise) ----------------
__global__ void round_tf32_kernel(const float4* __restrict__ in, float4* __restrict__ out, int n4) {
    int i = blockIdx.x * blockDim.x + threadIdx.x;
    int st = gridDim.x * blockDim.x;
    for (; i < n4; i += st) {
        float4 v = in[i];
        v.x = tf32r(v.x); v.y = tf32r(v.y); v.z = tf32r(v.z); v.w = tf32r(v.w);
        out[i] = v;
    }
}

// ---------------- row softmax over NBANK=8192, in place, tf32-rounded out ----------------
__global__ __launch_bounds__(256) void softmax_kernel(float* __restrict__ P)
{
    const int row = blockIdx.x;
    const int tid = threadIdx.x;
    float4* rowp = (float4*)(P + (long)row * NBANK);

    float4 v[8];
    float lmax = -3.0e38f;
#pragma unroll
    for (int j = 0; j < 8; j++) {
        v[j] = rowp[tid + j * 256];
        lmax = fmaxf(lmax, fmaxf(fmaxf(v[j].x, v[j].y), fmaxf(v[j].z, v[j].w)));
    }
    __shared__ float red[256];
    red[tid] = lmax;
    __syncthreads();
    for (int s = 128; s > 0; s >>= 1) {
        if (tid < s) red[tid] = fmaxf(red[tid], red[tid + s]);
        __syncthreads();
    }
    const float m = red[0];
    __syncthreads();
    float lsum = 0.f;
#pragma unroll
    for (int j = 0; j < 8; j++) {
        v[j].x = __expf(v[j].x - m); v[j].y = __expf(v[j].y - m);
        v[j].z = __expf(v[j].z - m); v[j].w = __expf(v[j].w - m);
        lsum += v[j].x + v[j].y + v[j].z + v[j].w;
    }
    red[tid] = lsum;
    __syncthreads();
    for (int s = 128; s > 0; s >>= 1) {
        if (tid < s) red[tid] += red[tid + s];
        __syncthreads();
    }
    const float inv = 1.f / red[0];
#pragma unroll
    for (int j = 0; j < 8; j++) {
        v[j].x = tf32r(v[j].x * inv); v[j].y = tf32r(v[j].y * inv);
        v[j].z = tf32r(v[j].z * inv); v[j].w = tf32r(v[j].w * inv);
        rowp[tid + j * 256] = v[j];
    }
}

// ---------------- cpair = f1*f2 ; LayerNorm ; PReLU ; tf32-round ----------------
__global__ __launch_bounds__(256) void gate_ln_kernel(
    const float* __restrict__ f1, const float* __restrict__ f2,
    const float* __restrict__ lnw, const float* __restrict__ lnb,
    const float* __restrict__ prelu_a, float* __restrict__ x)
{
    const int row = blockIdx.x;
    const int tid = threadIdx.x;
    const float4 a = ((const float4*)(f1 + (long)row * LAT))[tid];
    const float4 b = ((const float4*)(f2 + (long)row * LAT))[tid];
    float4 c;
    c.x = a.x * b.x; c.y = a.y * b.y; c.z = a.z * b.z; c.w = a.w * b.w;

    __shared__ float red[256];
    red[tid] = c.x + c.y + c.z + c.w;
    __syncthreads();
    for (int s = 128; s > 0; s >>= 1) {
        if (tid < s) red[tid] += red[tid + s];
        __syncthreads();
    }
    const float mu = red[0] * (1.f / LAT);
    __syncthreads();
    float dx = c.x - mu, dy = c.y - mu, dz = c.z - mu, dw = c.w - mu;
    red[tid] = dx * dx + dy * dy + dz * dz + dw * dw;
    __syncthreads();
    for (int s = 128; s > 0; s >>= 1) {
        if (tid < s) red[tid] += red[tid + s];
        __syncthreads();
    }
    const float rstd = rsqrtf(red[0] * (1.f / LAT) + 1e-5f);
    const float slope = prelu_a[0];
    const float4 w = ((const float4*)lnw)[tid];
    const float4 bb = ((const float4*)lnb)[tid];
    float4 o;
    o.x = dx * rstd * w.x + bb.x;
    o.y = dy * rstd * w.y + bb.y;
    o.z = dz * rstd * w.z + bb.z;
    o.w = dw * rstd * w.w + bb.w;
    o.x = o.x >= 0.f ? o.x : slope * o.x;
    o.y = o.y >= 0.f ? o.y : slope * o.y;
    o.z = o.z >= 0.f ? o.z : slope * o.z;
    o.w = o.w >= 0.f ? o.w : slope * o.w;
    o.x = tf32r(o.x); o.y = tf32r(o.y); o.z = tf32r(o.z); o.w = tf32r(o.w);
    ((float4*)(x + (long)row * LAT))[tid] = o;
}

// ---------------- launch ----------------
static inline void round_to(const float* in, float* out, long n) {
    int n4 = (int)(n / 4);
    int grid = (n4 + 255) / 256;
    if (grid > 4096) grid = 4096;
    round_tf32_kernel<<<grid, 256>>>((const float4*)in, (float4*)out, n4);
}

extern "C" void kernel_launch(void* const* d_in, const int* in_sizes, int n_in,
                              void* d_out, int out_size)
{
    const float* feat = (const float*)d_in[0];
    const float* bank = (const float*)d_in[1];
    const float* Wc1 = (const float*)d_in[2];  const float* bc1 = (const float*)d_in[3];
    const float* Wc2 = (const float*)d_in[4];  const float* bc2 = (const float*)d_in[5];
    const float* Wc3 = (const float*)d_in[6];  const float* bc3 = (const float*)d_in[7];
    const float* Wd1 = (const float*)d_in[8];  const float* bd1 = (const float*)d_in[9];
    const float* Wd2 = (const float*)d_in[10]; const float* bd2 = (const float*)d_in[11];
    const float* Wd3 = (const float*)d_in[12]; const float* bd3 = (const float*)d_in[13];
    const float* lnw = (const float*)d_in[14]; const float* lnb = (const float*)d_in[15];
    const float* pra = (const float*)d_in[16];
    const float* Wffn = (const float*)d_in[17]; const float* bffn = (const float*)d_in[18];
    float* out = (float*)d_out;

    float *rfeat, *rbank, *rw, *q1, *q2, *k1, *k2, *v1t, *v2t, *p, *f1, *f2, *x;
    cudaGetSymbolAddress((void**)&rfeat, g_rfeat);
    cudaGetSymbolAddress((void**)&rbank, g_rbank);
    cudaGetSymbolAddress((void**)&rw, g_rw);
    cudaGetSymbolAddress((void**)&q1, g_q1);
    cudaGetSymbolAddress((void**)&q2, g_q2);
    cudaGetSymbolAddress((void**)&k1, g_k1);
    cudaGetSymbolAddress((void**)&k2, g_k2);
    cudaGetSymbolAddress((void**)&v1t, g_v1t);
    cudaGetSymbolAddress((void**)&v2t, g_v2t);
    cudaGetSymbolAddress((void**)&p, g_p);
    cudaGetSymbolAddress((void**)&f1, g_f1);
    cudaGetSymbolAddress((void**)&f2, g_f2);
    cudaGetSymbolAddress((void**)&x, g_x);
    const long WSZ = (long)LAT * DIMIN;
    float* rWc1 = rw + 0 * WSZ;  float* rWc2 = rw + 1 * WSZ;  float* rWc3 = rw + 2 * WSZ;
    float* rWd1 = rw + 3 * WSZ;  float* rWd2 = rw + 4 * WSZ;  float* rWd3 = rw + 5 * WSZ;
    float* rWffn = rw + 6 * WSZ;

    cudaFuncSetAttribute(gemm_mma<false, true,  true >, cudaFuncAttributeMaxDynamicSharedMemorySize, GSMEM);
    cudaFuncSetAttribute(gemm_mma<true,  true,  true >, cudaFuncAttributeMaxDynamicSharedMemorySize, GSMEM);
    cudaFuncSetAttribute(gemm_mma<false, false, false>, cudaFuncAttributeMaxDynamicSharedMemorySize, GSMEM);
    cudaFuncSetAttribute(gemm_mma<false, true,  false>, cudaFuncAttributeMaxDynamicSharedMemorySize, GSMEM);

    // pre-round all GEMM inputs to tf32 (rna)
    round_to(feat, rfeat, (long)NROIS * QDIM_);
    round_to(bank, rbank, (long)NBANK * DIMIN);
    round_to(Wc1, rWc1, WSZ);  round_to(Wc2, rWc2, WSZ);  round_to(Wc3, rWc3, WSZ);
    round_to(Wd1, rWd1, WSZ);  round_to(Wd2, rWd2, WSZ);  round_to(Wd3, rWd3, WSZ);
    round_to(Wffn, rWffn, WSZ);

    const dim3 blk(256);
    const float inv_sqrt = 0.03125f;  // 1/sqrt(1024)

    // projections (q/k: col-bias; v computed transposed with row-bias)
    gemm_mma<false, true, true><<<dim3(LAT / BN, NROIS / BM), blk, GSMEM>>>(rfeat, rWc1, bc1, q1, NROIS, LAT, QDIM_, 1.f);
    gemm_mma<false, true, true><<<dim3(LAT / BN, NROIS / BM), blk, GSMEM>>>(rfeat, rWd1, bd1, q2, NROIS, LAT, QDIM_, 1.f);
    gemm_mma<false, true, true><<<dim3(LAT / BN, NBANK / BM), blk, GSMEM>>>(rbank, rWc2, bc2, k1, NBANK, LAT, DIMIN, 1.f);
    gemm_mma<false, true, true><<<dim3(LAT / BN, NBANK / BM), blk, GSMEM>>>(rbank, rWd2, bd2, k2, NBANK, LAT, DIMIN, 1.f);
    gemm_mma<true,  true, true><<<dim3(NBANK / BN, LAT / BM), blk, GSMEM>>>(rWc3, rbank, bc3, v1t, LAT, NBANK, DIMIN, 1.f);
    gemm_mma<true,  true, true><<<dim3(NBANK / BN, LAT / BM), blk, GSMEM>>>(rWd3, rbank, bd3, v2t, LAT, NBANK, DIMIN, 1.f);

    // branch 1
    gemm_mma<false, false, false><<<dim3(NBANK / BN, NROIS / BM), blk, GSMEM>>>(q1, k1, nullptr, p, NROIS, NBANK, LAT, inv_sqrt);
    softmax_kernel<<<NROIS, blk>>>(p);
    gemm_mma<false, false, false><<<dim3(LAT / BN, NROIS / BM), blk, GSMEM>>>(p, v1t, nullptr, f1, NROIS, LAT, NBANK, 1.f);

    // branch 2 (reuses score buffer; stream-ordered)
    gemm_mma<false, false, false><<<dim3(NBANK / BN, NROIS / BM), blk, GSMEM>>>(q2, k2, nullptr, p, NROIS, NBANK, LAT, inv_sqrt);
    softmax_kernel<<<NROIS, blk>>>(p);
    gemm_mma<false, false, false><<<dim3(LAT / BN, NROIS / BM), blk, GSMEM>>>(p, v2t, nullptr, f2, NROIS, LAT, NBANK, 1.f);

    // gate + LayerNorm + PReLU (rounds x to tf32)
    gate_ln_kernel<<<NROIS, blk>>>(f1, f2, lnw, lnb, pra, x);

    // FFN (fp32 out)
    gemm_mma<false, true, false><<<dim3(DIMIN / BN, NROIS / BM), blk, GSMEM>>>(x, rWffn, bffn, out, NROIS, DIMIN, LAT, 1.f);
}

// round 4
// speedup vs baseline: 3.5946x; 1.1018x over previous
#include <cuda_runtime.h>
#include <cstdint>

#define NROIS 4096
#define NBANK 8192
#define DIMIN 2048
#define QDIM_ 2048
#define LAT 1024

// ---------------- scratch (device globals: allocation-free) ----------------
__device__ float g_rfeat[NROIS * QDIM_];
__device__ float g_rbank[NBANK * DIMIN];
__device__ float g_rw[7][LAT * DIMIN];   // Wc1,Wc2,Wc3,Wd1,Wd2,Wd3,Wffn
__device__ float g_q1[NROIS * LAT];
__device__ float g_q2[NROIS * LAT];
__device__ float g_k1[NBANK * LAT];
__device__ float g_k2[NBANK * LAT];
__device__ float g_v1t[LAT * NBANK];
__device__ float g_v2t[LAT * NBANK];
__device__ float g_p[(long)NROIS * NBANK];
__device__ float g_f1[NROIS * LAT];
__device__ float g_f2[NROIS * LAT];
__device__ float g_x[NROIS * LAT];

// ---------------- helpers ----------------
__device__ __forceinline__ uint32_t smem_u32(const void* p) {
    uint32_t r;
    asm("{ .reg .u64 t; cvta.to.shared.u64 t, %1; cvt.u32.u64 %0, t; }" : "=r"(r) : "l"(p));
    return r;
}
__device__ __forceinline__ float tf32r(float x) {
    uint32_t u;
    asm("cvt.rna.tf32.f32 %0, %1;" : "=r"(u) : "f"(x));
    return __uint_as_float(u);
}
__device__ __forceinline__ void cp16(const float* smem_dst, const float* gsrc) {
    uint32_t a = smem_u32(smem_dst);
    asm volatile("cp.async.cg.shared.global [%0], [%1], 16;" :: "r"(a), "l"(gsrc) : "memory");
}
__device__ __forceinline__ void mma_tf32(float* d, const uint32_t* a, const uint32_t* b) {
    asm volatile(
        "mma.sync.aligned.m16n8k8.row.col.f32.tf32.tf32.f32 "
        "{%0,%1,%2,%3}, {%4,%5,%6,%7}, {%8,%9}, {%0,%1,%2,%3};"
        : "+f"(d[0]), "+f"(d[1]), "+f"(d[2]), "+f"(d[3])
        : "r"(a[0]), "r"(a[1]), "r"(a[2]), "r"(a[3]), "r"(b[0]), "r"(b[1]));
}

// ---------------- tf32 mma.sync GEMM: C = alpha * A[M,K] * B[N,K]^T (+bias) ----
#define BM 128
#define BN 128
#define BK 32
#define STAGES 3
#define LDS_ 36                       // padded floats per smem row (conflict-free)
#define TILE_F (128 * LDS_)           // 4608 floats per operand tile
#define STAGE_F (2 * TILE_F)          // A + B per stage
#define GSMEM (STAGES * STAGE_F * 4)  // 110592 bytes -> 2 CTAs/SM

template <bool ROWBIAS, bool HASBIAS, bool ROUND_OUT>
__global__ __launch_bounds__(256, 2)
void gemm_mma(const float* __restrict__ A, const float* __restrict__ B,
              const float* __restrict__ bias, float* __restrict__ C,
              int M, int N, int K, float alpha)
{
    extern __shared__ float sm[];
    const int tid = threadIdx.x;
    const int lane = tid & 31;
    const int wid = tid >> 5;
    const int wm = (wid >> 2) * 64;   // warp M offset (2 warps in M)
    const int wn = (wid & 3) * 32;    // warp N offset (4 warps in N)
    const long cRow = (long)blockIdx.y * BM;
    const long cCol = (long)blockIdx.x * BN;
    const int iters = K / BK;

    const float* Abase = A + cRow * (long)K;
    const float* Bbase = B + cCol * (long)K;

    auto load_stage = [&](int j, int s) {
        const float* Ag = Abase + (long)j * BK;
        const float* Bg = Bbase + (long)j * BK;
        float* Ast = sm + s * STAGE_F;
        float* Bst = Ast + TILE_F;
#pragma unroll
        for (int n = 0; n < 4; n++) {
            int c = tid + n * 256;           // 0..1023
            int row = c >> 3, ci = c & 7;    // 128 rows x 8 16B-chunks
            cp16(Ast + row * LDS_ + ci * 4, Ag + (long)row * K + ci * 4);
        }
#pragma unroll
        for (int n = 0; n < 4; n++) {
            int c = tid + n * 256;
            int row = c >> 3, ci = c & 7;
            cp16(Bst + row * LDS_ + ci * 4, Bg + (long)row * K + ci * 4);
        }
        asm volatile("cp.async.commit_group;" ::: "memory");
    };

    float acc[4][4][4];
#pragma unroll
    for (int mi = 0; mi < 4; mi++)
#pragma unroll
        for (int ni = 0; ni < 4; ni++)
#pragma unroll
            for (int r = 0; r < 4; r++) acc[mi][ni][r] = 0.f;

#pragma unroll
    for (int j = 0; j < STAGES - 1; j++) load_stage(j, j);

    for (int i = 0; i < iters; i++) {
        asm volatile("cp.async.wait_group %0;" :: "n"(STAGES - 2) : "memory");
        __syncthreads();

        const int jn = i + STAGES - 1;
        if (jn < iters) load_stage(jn, jn % STAGES);

        const uint32_t* Au = (const uint32_t*)(sm + (i % STAGES) * STAGE_F);
        const uint32_t* Bu = Au + TILE_F;

#pragma unroll
        for (int ks = 0; ks < 4; ks++) {
            const int kq = ks * 8 + (lane & 3);
            uint32_t a[4][4];
#pragma unroll
            for (int mi = 0; mi < 4; mi++) {
                const int r0 = wm + mi * 16 + (lane >> 2);
                a[mi][0] = Au[r0 * LDS_ + kq];
                a[mi][1] = Au[(r0 + 8) * LDS_ + kq];
                a[mi][2] = Au[r0 * LDS_ + kq + 4];
                a[mi][3] = Au[(r0 + 8) * LDS_ + kq + 4];
            }
            uint32_t b[4][2];
#pragma unroll
            for (int ni = 0; ni < 4; ni++) {
                const int c0 = wn + ni * 8 + (lane >> 2);
                b[ni][0] = Bu[c0 * LDS_ + kq];
                b[ni][1] = Bu[c0 * LDS_ + kq + 4];
            }
#pragma unroll
            for (int mi = 0; mi < 4; mi++)
#pragma unroll
                for (int ni = 0; ni < 4; ni++)
                    mma_tf32(acc[mi][ni], a[mi], b[ni]);
        }
    }

    // epilogue: direct register -> gmem
#pragma unroll
    for (int mi = 0; mi < 4; mi++) {
        const long rg = cRow + wm + mi * 16 + (lane >> 2);
        float rb0 = 0.f, rb1 = 0.f;
        if (ROWBIAS && HASBIAS) { rb0 = __ldg(&bias[rg]); rb1 = __ldg(&bias[rg + 8]); }
#pragma unroll
        for (int ni = 0; ni < 4; ni++) {
            const long cg = cCol + wn + ni * 8 + (lane & 3) * 2;
            float v0 = alpha * acc[mi][ni][0];
            float v1 = alpha * acc[mi][ni][1];
            float v2 = alpha * acc[mi][ni][2];
            float v3 = alpha * acc[mi][ni][3];
            if (HASBIAS) {
                if (ROWBIAS) { v0 += rb0; v1 += rb0; v2 += rb1; v3 += rb1; }
                else {
                    float cb0 = __ldg(&bias[cg]), cb1 = __ldg(&bias[cg + 1]);
                    v0 += cb0; v1 += cb1; v2 += cb0; v3 += cb1;
                }
            }
            if (ROUND_OUT) { v0 = tf32r(v0); v1 = tf32r(v1); v2 = tf32r(v2); v3 = tf32r(v3); }
            float2 lo; lo.x = v0; lo.y = v1;
            float2 hi; hi.x = v2; hi.y = v3;
            *(float2*)&C[rg * (long)N + cg] = lo;
            *(float2*)&C[(rg + 8) * (long)N + cg] = hi;
        }
    }
}

// ---------------- tf32 pre-round ----------------
__global__ void round_tf32_kernel(const float4* __restrict__ in, float4* __restrict__ out, int n4) {
    int i = blockIdx.x * blockDim.x + threadIdx.x;
    int st = gridDim.x * blockDim.x;
    for (; i < n4; i += st) {
        float4 v = in[i];
        v.x = tf32r(v.x); v.y = tf32r(v.y); v.z = tf32r(v.z); v.w = tf32r(v.w);
        out[i] = v;
    }
}

// fused weight rounding: 7 tensors of LAT*DIMIN floats, blockIdx.y selects
struct WPtrs { const float4* in[7]; float4* out[7]; };
__global__ void round_w_kernel(WPtrs wp, int n4) {
    const float4* in = wp.in[blockIdx.y];
    float4* out = wp.out[blockIdx.y];
    int i = blockIdx.x * blockDim.x + threadIdx.x;
    int st = gridDim.x * blockDim.x;
    for (; i < n4; i += st) {
        float4 v = in[i];
        v.x = tf32r(v.x); v.y = tf32r(v.y); v.z = tf32r(v.z); v.w = tf32r(v.w);
        out[i] = v;
    }
}

// ---------------- row softmax over NBANK=8192, in place, tf32-rounded out ----------------
__global__ __launch_bounds__(256) void softmax_kernel(float* __restrict__ P)
{
    const int row = blockIdx.x;
    const int tid = threadIdx.x;
    float4* rowp = (float4*)(P + (long)row * NBANK);

    float4 v[8];
    float lmax = -3.0e38f;
#pragma unroll
    for (int j = 0; j < 8; j++) {
        v[j] = rowp[tid + j * 256];
        lmax = fmaxf(lmax, fmaxf(fmaxf(v[j].x, v[j].y), fmaxf(v[j].z, v[j].w)));
    }
    __shared__ float red[256];
    red[tid] = lmax;
    __syncthreads();
    for (int s = 128; s > 0; s >>= 1) {
        if (tid < s) red[tid] = fmaxf(red[tid], red[tid + s]);
        __syncthreads();
    }
    const float m = red[0];
    __syncthreads();
    float lsum = 0.f;
#pragma unroll
    for (int j = 0; j < 8; j++) {
        v[j].x = __expf(v[j].x - m); v[j].y = __expf(v[j].y - m);
        v[j].z = __expf(v[j].z - m); v[j].w = __expf(v[j].w - m);
        lsum += v[j].x + v[j].y + v[j].z + v[j].w;
    }
    red[tid] = lsum;
    __syncthreads();
    for (int s = 128; s > 0; s >>= 1) {
        if (tid < s) red[tid] += red[tid + s];
        __syncthreads();
    }
    const float inv = 1.f / red[0];
#pragma unroll
    for (int j = 0; j < 8; j++) {
        v[j].x = tf32r(v[j].x * inv); v[j].y = tf32r(v[j].y * inv);
        v[j].z = tf32r(v[j].z * inv); v[j].w = tf32r(v[j].w * inv);
        rowp[tid + j * 256] = v[j];
    }
}

// ---------------- cpair = f1*f2 ; LayerNorm ; PReLU ; tf32-round ----------------
__global__ __launch_bounds__(256) void gate_ln_kernel(
    const float* __restrict__ f1, const float* __restrict__ f2,
    const float* __restrict__ lnw, const float* __restrict__ lnb,
    const float* __restrict__ prelu_a, float* __restrict__ x)
{
    const int row = blockIdx.x;
    const int tid = threadIdx.x;
    const float4 a = ((const float4*)(f1 + (long)row * LAT))[tid];
    const float4 b = ((const float4*)(f2 + (long)row * LAT))[tid];
    float4 c;
    c.x = a.x * b.x; c.y = a.y * b.y; c.z = a.z * b.z; c.w = a.w * b.w;

    __shared__ float red[256];
    red[tid] = c.x + c.y + c.z + c.w;
    __syncthreads();
    for (int s = 128; s > 0; s >>= 1) {
        if (tid < s) red[tid] += red[tid + s];
        __syncthreads();
    }
    const float mu = red[0] * (1.f / LAT);
    __syncthreads();
    float dx = c.x - mu, dy = c.y - mu, dz = c.z - mu, dw = c.w - mu;
    red[tid] = dx * dx + dy * dy + dz * dz + dw * dw;
    __syncthreads();
    for (int s = 128; s > 0; s >>= 1) {
        if (tid < s) red[tid] += red[tid + s];
        __syncthreads();
    }
    const float rstd = rsqrtf(red[0] * (1.f / LAT) + 1e-5f);
    const float slope = prelu_a[0];
    const float4 w = ((const float4*)lnw)[tid];
    const float4 bb = ((const float4*)lnb)[tid];
    float4 o;
    o.x = dx * rstd * w.x + bb.x;
    o.y = dy * rstd * w.y + bb.y;
    o.z = dz * rstd * w.z + bb.z;
    o.w = dw * rstd * w.w + bb.w;
    o.x = o.x >= 0.f ? o.x : slope * o.x;
    o.y = o.y >= 0.f ? o.y : slope * o.y;
    o.z = o.z >= 0.f ? o.z : slope * o.z;
    o.w = o.w >= 0.f ? o.w : slope * o.w;
    o.x = tf32r(o.x); o.y = tf32r(o.y); o.z = tf32r(o.z); o.w = tf32r(o.w);
    ((float4*)(x + (long)row * LAT))[tid] = o;
}

// ---------------- launch ----------------
extern "C" void kernel_launch(void* const* d_in, const int* in_sizes, int n_in,
                              void* d_out, int out_size)
{
    const float* feat = (const float*)d_in[0];
    const float* bank = (const float*)d_in[1];
    const float* Wc1 = (const float*)d_in[2];  const float* bc1 = (const float*)d_in[3];
    const float* Wc2 = (const float*)d_in[4];  const float* bc2 = (const float*)d_in[5];
    const float* Wc3 = (const float*)d_in[6];  const float* bc3 = (const float*)d_in[7];
    const float* Wd1 = (const float*)d_in[8];  const float* bd1 = (const float*)d_in[9];
    const float* Wd2 = (const float*)d_in[10]; const float* bd2 = (const float*)d_in[11];
    const float* Wd3 = (const float*)d_in[12]; const float* bd3 = (const float*)d_in[13];
    const float* lnw = (const float*)d_in[14]; const float* lnb = (const float*)d_in[15];
    const float* pra = (const float*)d_in[16];
    const float* Wffn = (const float*)d_in[17]; const float* bffn = (const float*)d_in[18];
    float* out = (float*)d_out;

    float *rfeat, *rbank, *rw, *q1, *q2, *k1, *k2, *v1t, *v2t, *p, *f1, *f2, *x;
    cudaGetSymbolAddress((void**)&rfeat, g_rfeat);
    cudaGetSymbolAddress((void**)&rbank, g_rbank);
    cudaGetSymbolAddress((void**)&rw, g_rw);
    cudaGetSymbolAddress((void**)&q1, g_q1);
    cudaGetSymbolAddress((void**)&q2, g_q2);
    cudaGetSymbolAddress((void**)&k1, g_k1);
    cudaGetSymbolAddress((void**)&k2, g_k2);
    cudaGetSymbolAddress((void**)&v1t, g_v1t);
    cudaGetSymbolAddress((void**)&v2t, g_v2t);
    cudaGetSymbolAddress((void**)&p, g_p);
    cudaGetSymbolAddress((void**)&f1, g_f1);
    cudaGetSymbolAddress((void**)&f2, g_f2);
    cudaGetSymbolAddress((void**)&x, g_x);
    const long WSZ = (long)LAT * DIMIN;
    float* rWc1 = rw + 0 * WSZ;  float* rWc2 = rw + 1 * WSZ;  float* rWc3 = rw + 2 * WSZ;
    float* rWd1 = rw + 3 * WSZ;  float* rWd2 = rw + 4 * WSZ;  float* rWd3 = rw + 5 * WSZ;
    float* rWffn = rw + 6 * WSZ;

    cudaFuncSetAttribute(gemm_mma<false, true,  true >, cudaFuncAttributeMaxDynamicSharedMemorySize, GSMEM);
    cudaFuncSetAttribute(gemm_mma<true,  true,  true >, cudaFuncAttributeMaxDynamicSharedMemorySize, GSMEM);
    cudaFuncSetAttribute(gemm_mma<false, false, false>, cudaFuncAttributeMaxDynamicSharedMemorySize, GSMEM);
    cudaFuncSetAttribute(gemm_mma<false, true,  false>, cudaFuncAttributeMaxDynamicSharedMemorySize, GSMEM);

    // pre-round all GEMM inputs to tf32 (rna): 3 launches
    round_tf32_kernel<<<2048, 256>>>((const float4*)feat, (float4*)rfeat, (int)((long)NROIS * QDIM_ / 4));
    round_tf32_kernel<<<4096, 256>>>((const float4*)bank, (float4*)rbank, (int)((long)NBANK * DIMIN / 4));
    {
        WPtrs wp;
        wp.in[0] = (const float4*)Wc1;  wp.out[0] = (float4*)rWc1;
        wp.in[1] = (const float4*)Wc2;  wp.out[1] = (float4*)rWc2;
        wp.in[2] = (const float4*)Wc3;  wp.out[2] = (float4*)rWc3;
        wp.in[3] = (const float4*)Wd1;  wp.out[3] = (float4*)rWd1;
        wp.in[4] = (const float4*)Wd2;  wp.out[4] = (float4*)rWd2;
        wp.in[5] = (const float4*)Wd3;  wp.out[5] = (float4*)rWd3;
        wp.in[6] = (const float4*)Wffn; wp.out[6] = (float4*)rWffn;
        round_w_kernel<<<dim3(512, 7), 256>>>(wp, (int)(WSZ / 4));
    }

    const dim3 blk(256);
    const float inv_sqrt = 0.03125f;  // 1/sqrt(1024)

    // projections (q/k: col-bias; v computed transposed with row-bias)
    gemm_mma<false, true, true><<<dim3(LAT / BN, NROIS / BM), blk, GSMEM>>>(rfeat, rWc1, bc1, q1, NROIS, LAT, QDIM_, 1.f);
    gemm_mma<false, true, true><<<dim3(LAT / BN, NROIS / BM), blk, GSMEM>>>(rfeat, rWd1, bd1, q2, NROIS, LAT, QDIM_, 1.f);
    gemm_mma<false, true, true><<<dim3(LAT / BN, NBANK / BM), blk, GSMEM>>>(rbank, rWc2, bc2, k1, NBANK, LAT, DIMIN, 1.f);
    gemm_mma<false, true, true><<<dim3(LAT / BN, NBANK / BM), blk, GSMEM>>>(rbank, rWd2, bd2, k2, NBANK, LAT, DIMIN, 1.f);
    gemm_mma<true,  true, true><<<dim3(NBANK / BN, LAT / BM), blk, GSMEM>>>(rWc3, rbank, bc3, v1t, LAT, NBANK, DIMIN, 1.f);
    gemm_mma<true,  true, true><<<dim3(NBANK / BN, LAT / BM), blk, GSMEM>>>(rWd3, rbank, bd3, v2t, LAT, NBANK, DIMIN, 1.f);

    // branch 1
    gemm_mma<false, false, false><<<dim3(NBANK / BN, NROIS / BM), blk, GSMEM>>>(q1, k1, nullptr, p, NROIS, NBANK, LAT, inv_sqrt);
    softmax_kernel<<<NROIS, blk>>>(p);
    gemm_mma<false, false, false><<<dim3(LAT / BN, NROIS / BM), blk, GSMEM>>>(p, v1t, nullptr, f1, NROIS, LAT, NBANK, 1.f);

    // branch 2 (reuses score buffer; stream-ordered)
    gemm_mma<false, false, false><<<dim3(NBANK / BN, NROIS / BM), blk, GSMEM>>>(q2, k2, nullptr, p, NROIS, NBANK, LAT, inv_sqrt);
    softmax_kernel<<<NROIS, blk>>>(p);
    gemm_mma<false, false, false><<<dim3(LAT / BN, NROIS / BM), blk, GSMEM>>>(p, v2t, nullptr, f2, NROIS, LAT, NBANK, 1.f);

    // gate + LayerNorm + PReLU (rounds x to tf32)
    gate_ln_kernel<<<NROIS, blk>>>(f1, f2, lnw, lnb, pra, x);

    // FFN (fp32 out)
    gemm_mma<false, true, false><<<dim3(DIMIN / BN, NROIS / BM), blk, GSMEM>>>(x, rWffn, bffn, out, NROIS, DIMIN, LAT, 1.f);
}

// round 5
// speedup vs baseline: 3.8351x; 1.0669x over previous
#include <cuda_runtime.h>
#include <cstdint>

#define NROIS 4096
#define NBANK 8192
#define DIMIN 2048
#define QDIM_ 2048
#define LAT 1024

// ---------------- scratch (device globals: allocation-free) ----------------
__device__ float g_rfeat[NROIS * QDIM_];
__device__ float g_rbank[NBANK * DIMIN];
__device__ float g_rw[7][LAT * DIMIN];   // Wc1,Wc2,Wc3,Wd1,Wd2,Wd3,Wffn
__device__ float g_q1[NROIS * LAT];
__device__ float g_q2[NROIS * LAT];
__device__ float g_k1[NBANK * LAT];
__device__ float g_k2[NBANK * LAT];
__device__ float g_v1t[LAT * NBANK];
__device__ float g_v2t[LAT * NBANK];
__device__ float g_p[(long)NROIS * NBANK];
__device__ float g_f1[NROIS * LAT];
__device__ float g_f2[NROIS * LAT];
__device__ float g_x[NROIS * LAT];

// ---------------- helpers ----------------
__device__ __forceinline__ uint32_t smem_u32(const void* p) {
    uint32_t r;
    asm("{ .reg .u64 t; cvta.to.shared.u64 t, %1; cvt.u32.u64 %0, t; }" : "=r"(r) : "l"(p));
    return r;
}
__device__ __forceinline__ float tf32r(float x) {
    uint32_t u;
    asm("cvt.rna.tf32.f32 %0, %1;" : "=r"(u) : "f"(x));
    return __uint_as_float(u);
}
__device__ __forceinline__ void cp16(const float* smem_dst, const float* gsrc) {
    uint32_t a = smem_u32(smem_dst);
    asm volatile("cp.async.cg.shared.global [%0], [%1], 16;" :: "r"(a), "l"(gsrc) : "memory");
}
__device__ __forceinline__ void mma_tf32(float* d, const uint32_t* a, const uint32_t* b) {
    asm volatile(
        "mma.sync.aligned.m16n8k8.row.col.f32.tf32.tf32.f32 "
        "{%0,%1,%2,%3}, {%4,%5,%6,%7}, {%8,%9}, {%0,%1,%2,%3};"
        : "+f"(d[0]), "+f"(d[1]), "+f"(d[2]), "+f"(d[3])
        : "r"(a[0]), "r"(a[1]), "r"(a[2]), "r"(a[3]), "r"(b[0]), "r"(b[1]));
}

// ---------------- tf32 mma.sync GEMM: C = alpha * A[M,K] * B[N,K]^T (+bias) ----
// BM=128, BN=256, BK=32; 8 warps, warp tile 64x64; 1 CTA/SM, deep ILP.
#define BM 128
#define BN 256
#define BK 32
#define STAGES 3
#define LDS_ 36                        // padded floats per smem row (conflict-free)
#define A_TILE_F (128 * LDS_)          // 4608 floats
#define B_TILE_F (256 * LDS_)          // 9216 floats
#define STAGE_F (A_TILE_F + B_TILE_F)  // 13824 floats
#define GSMEM (STAGES * STAGE_F * 4)   // 165888 bytes -> 1 CTA/SM

template <bool ROWBIAS, bool HASBIAS, bool ROUND_OUT>
__global__ __launch_bounds__(256, 1)
void gemm_mma(const float* __restrict__ A, const float* __restrict__ B,
              const float* __restrict__ bias, float* __restrict__ C,
              int M, int N, int K, float alpha)
{
    extern __shared__ float sm[];
    const int tid = threadIdx.x;
    const int lane = tid & 31;
    const int wid = tid >> 5;
    const int wm = (wid >> 2) * 64;   // warp M offset (2 warps in M)
    const int wn = (wid & 3) * 64;    // warp N offset (4 warps in N)
    const long cRow = (long)blockIdx.y * BM;
    const long cCol = (long)blockIdx.x * BN;
    const int iters = K / BK;

    const float* Abase = A + cRow * (long)K;
    const float* Bbase = B + cCol * (long)K;

    auto load_stage = [&](int j, int s) {
        const float* Ag = Abase + (long)j * BK;
        const float* Bg = Bbase + (long)j * BK;
        float* Ast = sm + s * STAGE_F;
        float* Bst = Ast + A_TILE_F;
#pragma unroll
        for (int n = 0; n < 4; n++) {            // A: 128 rows x 8 16B-chunks
            int c = tid + n * 256;
            int row = c >> 3, ci = c & 7;
            cp16(Ast + row * LDS_ + ci * 4, Ag + (long)row * K + ci * 4);
        }
#pragma unroll
        for (int n = 0; n < 8; n++) {            // B: 256 rows x 8 16B-chunks
            int c = tid + n * 256;
            int row = c >> 3, ci = c & 7;
            cp16(Bst + row * LDS_ + ci * 4, Bg + (long)row * K + ci * 4);
        }
        asm volatile("cp.async.commit_group;" ::: "memory");
    };

    float acc[4][8][4];
#pragma unroll
    for (int mi = 0; mi < 4; mi++)
#pragma unroll
        for (int ni = 0; ni < 8; ni++)
#pragma unroll
            for (int r = 0; r < 4; r++) acc[mi][ni][r] = 0.f;

#pragma unroll
    for (int j = 0; j < STAGES - 1; j++) load_stage(j, j);

    for (int i = 0; i < iters; i++) {
        asm volatile("cp.async.wait_group %0;" :: "n"(STAGES - 2) : "memory");
        __syncthreads();

        const int jn = i + STAGES - 1;
        if (jn < iters) load_stage(jn, jn % STAGES);

        const uint32_t* Au = (const uint32_t*)(sm + (i % STAGES) * STAGE_F);
        const uint32_t* Bu = Au + A_TILE_F;

#pragma unroll
        for (int ks = 0; ks < 4; ks++) {
            const int kq = ks * 8 + (lane & 3);
            uint32_t a[4][4];
#pragma unroll
            for (int mi = 0; mi < 4; mi++) {
                const int r0 = wm + mi * 16 + (lane >> 2);
                a[mi][0] = Au[r0 * LDS_ + kq];
                a[mi][1] = Au[(r0 + 8) * LDS_ + kq];
                a[mi][2] = Au[r0 * LDS_ + kq + 4];
                a[mi][3] = Au[(r0 + 8) * LDS_ + kq + 4];
            }
            uint32_t b[8][2];
#pragma unroll
            for (int ni = 0; ni < 8; ni++) {
                const int c0 = wn + ni * 8 + (lane >> 2);
                b[ni][0] = Bu[c0 * LDS_ + kq];
                b[ni][1] = Bu[c0 * LDS_ + kq + 4];
            }
#pragma unroll
            for (int mi = 0; mi < 4; mi++)
#pragma unroll
                for (int ni = 0; ni < 8; ni++)
                    mma_tf32(acc[mi][ni], a[mi], b[ni]);
        }
    }

    // epilogue: direct register -> gmem
#pragma unroll
    for (int mi = 0; mi < 4; mi++) {
        const long rg = cRow + wm + mi * 16 + (lane >> 2);
        float rb0 = 0.f, rb1 = 0.f;
        if (ROWBIAS && HASBIAS) { rb0 = __ldg(&bias[rg]); rb1 = __ldg(&bias[rg + 8]); }
#pragma unroll
        for (int ni = 0; ni < 8; ni++) {
            const long cg = cCol + wn + ni * 8 + (lane & 3) * 2;
            float v0 = alpha * acc[mi][ni][0];
            float v1 = alpha * acc[mi][ni][1];
            float v2 = alpha * acc[mi][ni][2];
            float v3 = alpha * acc[mi][ni][3];
            if (HASBIAS) {
                if (ROWBIAS) { v0 += rb0; v1 += rb0; v2 += rb1; v3 += rb1; }
                else {
                    float cb0 = __ldg(&bias[cg]), cb1 = __ldg(&bias[cg + 1]);
                    v0 += cb0; v1 += cb1; v2 += cb0; v3 += cb1;
                }
            }
            if (ROUND_OUT) { v0 = tf32r(v0); v1 = tf32r(v1); v2 = tf32r(v2); v3 = tf32r(v3); }
            float2 lo; lo.x = v0; lo.y = v1;
            float2 hi; hi.x = v2; hi.y = v3;
            *(float2*)&C[rg * (long)N + cg] = lo;
            *(float2*)&C[(rg + 8) * (long)N + cg] = hi;
        }
    }
}

// ---------------- tf32 pre-round ----------------
__global__ void round_tf32_kernel(const float4* __restrict__ in, float4* __restrict__ out, int n4) {
    int i = blockIdx.x * blockDim.x + threadIdx.x;
    int st = gridDim.x * blockDim.x;
    for (; i < n4; i += st) {
        float4 v = in[i];
        v.x = tf32r(v.x); v.y = tf32r(v.y); v.z = tf32r(v.z); v.w = tf32r(v.w);
        out[i] = v;
    }
}

// fused weight rounding: 7 tensors of LAT*DIMIN floats, blockIdx.y selects
struct WPtrs { const float4* in[7]; float4* out[7]; };
__global__ void round_w_kernel(WPtrs wp, int n4) {
    const float4* in = wp.in[blockIdx.y];
    float4* out = wp.out[blockIdx.y];
    int i = blockIdx.x * blockDim.x + threadIdx.x;
    int st = gridDim.x * blockDim.x;
    for (; i < n4; i += st) {
        float4 v = in[i];
        v.x = tf32r(v.x); v.y = tf32r(v.y); v.z = tf32r(v.z); v.w = tf32r(v.w);
        out[i] = v;
    }
}

// ---------------- row softmax over NBANK=8192, in place, tf32-rounded out ----------------
__global__ __launch_bounds__(256) void softmax_kernel(float* __restrict__ P)
{
    const int row = blockIdx.x;
    const int tid = threadIdx.x;
    float4* rowp = (float4*)(P + (long)row * NBANK);

    float4 v[8];
    float lmax = -3.0e38f;
#pragma unroll
    for (int j = 0; j < 8; j++) {
        v[j] = rowp[tid + j * 256];
        lmax = fmaxf(lmax, fmaxf(fmaxf(v[j].x, v[j].y), fmaxf(v[j].z, v[j].w)));
    }
    __shared__ float red[256];
    red[tid] = lmax;
    __syncthreads();
    for (int s = 128; s > 0; s >>= 1) {
        if (tid < s) red[tid] = fmaxf(red[tid], red[tid + s]);
        __syncthreads();
    }
    const float m = red[0];
    __syncthreads();
    float lsum = 0.f;
#pragma unroll
    for (int j = 0; j < 8; j++) {
        v[j].x = __expf(v[j].x - m); v[j].y = __expf(v[j].y - m);
        v[j].z = __expf(v[j].z - m); v[j].w = __expf(v[j].w - m);
        lsum += v[j].x + v[j].y + v[j].z + v[j].w;
    }
    red[tid] = lsum;
    __syncthreads();
    for (int s = 128; s > 0; s >>= 1) {
        if (tid < s) red[tid] += red[tid + s];
        __syncthreads();
    }
    const float inv = 1.f / red[0];
#pragma unroll
    for (int j = 0; j < 8; j++) {
        v[j].x = tf32r(v[j].x * inv); v[j].y = tf32r(v[j].y * inv);
        v[j].z = tf32r(v[j].z * inv); v[j].w = tf32r(v[j].w * inv);
        rowp[tid + j * 256] = v[j];
    }
}

// ---------------- cpair = f1*f2 ; LayerNorm ; PReLU ; tf32-round ----------------
__global__ __launch_bounds__(256) void gate_ln_kernel(
    const float* __restrict__ f1, const float* __restrict__ f2,
    const float* __restrict__ lnw, const float* __restrict__ lnb,
    const float* __restrict__ prelu_a, float* __restrict__ x)
{
    const int row = blockIdx.x;
    const int tid = threadIdx.x;
    const float4 a = ((const float4*)(f1 + (long)row * LAT))[tid];
    const float4 b = ((const float4*)(f2 + (long)row * LAT))[tid];
    float4 c;
    c.x = a.x * b.x; c.y = a.y * b.y; c.z = a.z * b.z; c.w = a.w * b.w;

    __shared__ float red[256];
    red[tid] = c.x + c.y + c.z + c.w;
    __syncthreads();
    for (int s = 128; s > 0; s >>= 1) {
        if (tid < s) red[tid] += red[tid + s];
        __syncthreads();
    }
    const float mu = red[0] * (1.f / LAT);
    __syncthreads();
    float dx = c.x - mu, dy = c.y - mu, dz = c.z - mu, dw = c.w - mu;
    red[tid] = dx * dx + dy * dy + dz * dz + dw * dw;
    __syncthreads();
    for (int s = 128; s > 0; s >>= 1) {
        if (tid < s) red[tid] += red[tid + s];
        __syncthreads();
    }
    const float rstd = rsqrtf(red[0] * (1.f / LAT) + 1e-5f);
    const float slope = prelu_a[0];
    const float4 w = ((const float4*)lnw)[tid];
    const float4 bb = ((const float4*)lnb)[tid];
    float4 o;
    o.x = dx * rstd * w.x + bb.x;
    o.y = dy * rstd * w.y + bb.y;
    o.z = dz * rstd * w.z + bb.z;
    o.w = dw * rstd * w.w + bb.w;
    o.x = o.x >= 0.f ? o.x : slope * o.x;
    o.y = o.y >= 0.f ? o.y : slope * o.y;
    o.z = o.z >= 0.f ? o.z : slope * o.z;
    o.w = o.w >= 0.f ? o.w : slope * o.w;
    o.x = tf32r(o.x); o.y = tf32r(o.y); o.z = tf32r(o.z); o.w = tf32r(o.w);
    ((float4*)(x + (long)row * LAT))[tid] = o;
}

// ---------------- launch ----------------
extern "C" void kernel_launch(void* const* d_in, const int* in_sizes, int n_in,
                              void* d_out, int out_size)
{
    const float* feat = (const float*)d_in[0];
    const float* bank = (const float*)d_in[1];
    const float* Wc1 = (const float*)d_in[2];  const float* bc1 = (const float*)d_in[3];
    const float* Wc2 = (const float*)d_in[4];  const float* bc2 = (const float*)d_in[5];
    const float* Wc3 = (const float*)d_in[6];  const float* bc3 = (const float*)d_in[7];
    const float* Wd1 = (const float*)d_in[8];  const float* bd1 = (const float*)d_in[9];
    const float* Wd2 = (const float*)d_in[10]; const float* bd2 = (const float*)d_in[11];
    const float* Wd3 = (const float*)d_in[12]; const float* bd3 = (const float*)d_in[13];
    const float* lnw = (const float*)d_in[14]; const float* lnb = (const float*)d_in[15];
    const float* pra = (const float*)d_in[16];
    const float* Wffn = (const float*)d_in[17]; const float* bffn = (const float*)d_in[18];
    float* out = (float*)d_out;

    float *rfeat, *rbank, *rw, *q1, *q2, *k1, *k2, *v1t, *v2t, *p, *f1, *f2, *x;
    cudaGetSymbolAddress((void**)&rfeat, g_rfeat);
    cudaGetSymbolAddress((void**)&rbank, g_rbank);
    cudaGetSymbolAddress((void**)&rw, g_rw);
    cudaGetSymbolAddress((void**)&q1, g_q1);
    cudaGetSymbolAddress((void**)&q2, g_q2);
    cudaGetSymbolAddress((void**)&k1, g_k1);
    cudaGetSymbolAddress((void**)&k2, g_k2);
    cudaGetSymbolAddress((void**)&v1t, g_v1t);
    cudaGetSymbolAddress((void**)&v2t, g_v2t);
    cudaGetSymbolAddress((void**)&p, g_p);
    cudaGetSymbolAddress((void**)&f1, g_f1);
    cudaGetSymbolAddress((void**)&f2, g_f2);
    cudaGetSymbolAddress((void**)&x, g_x);
    const long WSZ = (long)LAT * DIMIN;
    float* rWc1 = rw + 0 * WSZ;  float* rWc2 = rw + 1 * WSZ;  float* rWc3 = rw + 2 * WSZ;
    float* rWd1 = rw + 3 * WSZ;  float* rWd2 = rw + 4 * WSZ;  float* rWd3 = rw + 5 * WSZ;
    float* rWffn = rw + 6 * WSZ;

    cudaFuncSetAttribute(gemm_mma<false, true,  true >, cudaFuncAttributeMaxDynamicSharedMemorySize, GSMEM);
    cudaFuncSetAttribute(gemm_mma<true,  true,  true >, cudaFuncAttributeMaxDynamicSharedMemorySize, GSMEM);
    cudaFuncSetAttribute(gemm_mma<false, false, false>, cudaFuncAttributeMaxDynamicSharedMemorySize, GSMEM);
    cudaFuncSetAttribute(gemm_mma<false, true,  false>, cudaFuncAttributeMaxDynamicSharedMemorySize, GSMEM);

    // pre-round all GEMM inputs to tf32 (rna): 3 launches
    round_tf32_kernel<<<2048, 256>>>((const float4*)feat, (float4*)rfeat, (int)((long)NROIS * QDIM_ / 4));
    round_tf32_kernel<<<4096, 256>>>((const float4*)bank, (float4*)rbank, (int)((long)NBANK * DIMIN / 4));
    {
        WPtrs wp;
        wp.in[0] = (const float4*)Wc1;  wp.out[0] = (float4*)rWc1;
        wp.in[1] = (const float4*)Wc2;  wp.out[1] = (float4*)rWc2;
        wp.in[2] = (const float4*)Wc3;  wp.out[2] = (float4*)rWc3;
        wp.in[3] = (const float4*)Wd1;  wp.out[3] = (float4*)rWd1;
        wp.in[4] = (const float4*)Wd2;  wp.out[4] = (float4*)rWd2;
        wp.in[5] = (const float4*)Wd3;  wp.out[5] = (float4*)rWd3;
        wp.in[6] = (const float4*)Wffn; wp.out[6] = (float4*)rWffn;
        round_w_kernel<<<dim3(512, 7), 256>>>(wp, (int)(WSZ / 4));
    }

    const dim3 blk(256);
    const float inv_sqrt = 0.03125f;  // 1/sqrt(1024)

    // projections (q/k: col-bias; v computed transposed with row-bias)
    gemm_mma<false, true, true><<<dim3(LAT / BN, NROIS / BM), blk, GSMEM>>>(rfeat, rWc1, bc1, q1, NROIS, LAT, QDIM_, 1.f);
    gemm_mma<false, true, true><<<dim3(LAT / BN, NROIS / BM), blk, GSMEM>>>(rfeat, rWd1, bd1, q2, NROIS, LAT, QDIM_, 1.f);
    gemm_mma<false, true, true><<<dim3(LAT / BN, NBANK / BM), blk, GSMEM>>>(rbank, rWc2, bc2, k1, NBANK, LAT, DIMIN, 1.f);
    gemm_mma<false, true, true><<<dim3(LAT / BN, NBANK / BM), blk, GSMEM>>>(rbank, rWd2, bd2, k2, NBANK, LAT, DIMIN, 1.f);
    gemm_mma<true,  true, true><<<dim3(NBANK / BN, LAT / BM), blk, GSMEM>>>(rWc3, rbank, bc3, v1t, LAT, NBANK, DIMIN, 1.f);
    gemm_mma<true,  true, true><<<dim3(NBANK / BN, LAT / BM), blk, GSMEM>>>(rWd3, rbank, bd3, v2t, LAT, NBANK, DIMIN, 1.f);

    // branch 1
    gemm_mma<false, false, false><<<dim3(NBANK / BN, NROIS / BM), blk, GSMEM>>>(q1, k1, nullptr, p, NROIS, NBANK, LAT, inv_sqrt);
    softmax_kernel<<<NROIS, blk>>>(p);
    gemm_mma<false, false, false><<<dim3(LAT / BN, NROIS / BM), blk, GSMEM>>>(p, v1t, nullptr, f1, NROIS, LAT, NBANK, 1.f);

    // branch 2 (reuses score buffer; stream-ordered)
    gemm_mma<false, false, false><<<dim3(NBANK / BN, NROIS / BM), blk, GSMEM>>>(q2, k2, nullptr, p, NROIS, NBANK, LAT, inv_sqrt);
    softmax_kernel<<<NROIS, blk>>>(p);
    gemm_mma<false, false, false><<<dim3(LAT / BN, NROIS / BM), blk, GSMEM>>>(p, v2t, nullptr, f2, NROIS, LAT, NBANK, 1.f);

    // gate + LayerNorm + PReLU (rounds x to tf32)
    gate_ln_kernel<<<NROIS, blk>>>(f1, f2, lnw, lnb, pra, x);

    // FFN (fp32 out)
    gemm_mma<false, true, false><<<dim3(DIMIN / BN, NROIS / BM), blk, GSMEM>>>(x, rWffn, bffn, out, NROIS, DIMIN, LAT, 1.f);
}

// round 6
// speedup vs baseline: 3.9561x; 1.0315x over previous
#include <cuda_runtime.h>
#include <cstdint>

#define NROIS 4096
#define NBANK 8192
#define DIMIN 2048
#define QDIM_ 2048
#define LAT 1024

// ---------------- scratch (device globals: allocation-free) ----------------
__device__ float g_rfeat[NROIS * QDIM_];
__device__ float g_rbank[NBANK * DIMIN];
__device__ float g_rw[7][LAT * DIMIN];   // Wc1,Wc2,Wc3,Wd1,Wd2,Wd3,Wffn
__device__ float g_q1[NROIS * LAT];
__device__ float g_q2[NROIS * LAT];
__device__ float g_k1[NBANK * LAT];
__device__ float g_k2[NBANK * LAT];
__device__ float g_v1t[LAT * NBANK];
__device__ float g_v2t[LAT * NBANK];
__device__ float g_p1[(long)NROIS * NBANK];
__device__ float g_p2[(long)NROIS * NBANK];
__device__ float g_f1[NROIS * LAT];
__device__ float g_f2[NROIS * LAT];
__device__ float g_x[NROIS * LAT];

// ---------------- helpers ----------------
__device__ __forceinline__ uint32_t smem_u32(const void* p) {
    uint32_t r;
    asm("{ .reg .u64 t; cvta.to.shared.u64 t, %1; cvt.u32.u64 %0, t; }" : "=r"(r) : "l"(p));
    return r;
}
__device__ __forceinline__ float tf32r(float x) {
    uint32_t u;
    asm("cvt.rna.tf32.f32 %0, %1;" : "=r"(u) : "f"(x));
    return __uint_as_float(u);
}
__device__ __forceinline__ void cp16(const float* smem_dst, const float* gsrc) {
    uint32_t a = smem_u32(smem_dst);
    asm volatile("cp.async.cg.shared.global [%0], [%1], 16;" :: "r"(a), "l"(gsrc) : "memory");
}
__device__ __forceinline__ void mma_tf32(float* d, const uint32_t* a, const uint32_t* b) {
    asm volatile(
        "mma.sync.aligned.m16n8k8.row.col.f32.tf32.tf32.f32 "
        "{%0,%1,%2,%3}, {%4,%5,%6,%7}, {%8,%9}, {%0,%1,%2,%3};"
        : "+f"(d[0]), "+f"(d[1]), "+f"(d[2]), "+f"(d[3])
        : "r"(a[0]), "r"(a[1]), "r"(a[2]), "r"(a[3]), "r"(b[0]), "r"(b[1]));
}
__device__ __forceinline__ void ldsm_x4(uint32_t* r, uint32_t addr) {
    asm volatile("ldmatrix.sync.aligned.m8n8.x4.shared.b16 {%0,%1,%2,%3}, [%4];"
        : "=r"(r[0]), "=r"(r[1]), "=r"(r[2]), "=r"(r[3]) : "r"(addr));
}
__device__ __forceinline__ void ldsm_x2(uint32_t* r, uint32_t addr) {
    asm volatile("ldmatrix.sync.aligned.m8n8.x2.shared.b16 {%0,%1}, [%2];"
        : "=r"(r[0]), "=r"(r[1]) : "r"(addr));
}

// ---------------- tf32 mma.sync GEMM: C = alpha * A[M,K] * B[N,K]^T (+bias) ----
// BM=128, BN=256, BK=32; 8 warps (2x4), warp tile 64x64; ldmatrix fragments.
// blockIdx.z selects one of 2 independent problems (same M,N,K).
#define BM 128
#define BN 256
#define BK 32
#define STAGES 3
#define LDS_ 36                        // padded floats per smem row (conflict-free)
#define A_TILE_F (128 * LDS_)
#define B_TILE_F (256 * LDS_)
#define STAGE_F (A_TILE_F + B_TILE_F)
#define GSMEM (STAGES * STAGE_F * 4)   // 165888 bytes -> 1 CTA/SM

struct GB2 {
    const float* A[2];
    const float* B[2];
    const float* bias[2];
    float* C[2];
};

template <bool ROWBIAS, bool HASBIAS, bool ROUND_OUT>
__global__ __launch_bounds__(256, 1)
void gemm_mma(GB2 gb, int M, int N, int K, float alpha)
{
    extern __shared__ float sm[];
    const int z = blockIdx.z;
    const float* __restrict__ A = gb.A[z];
    const float* __restrict__ B = gb.B[z];
    const float* __restrict__ bias = gb.bias[z];
    float* __restrict__ C = gb.C[z];

    const int tid = threadIdx.x;
    const int lane = tid & 31;
    const int wid = tid >> 5;
    const int wm = (wid >> 2) * 64;   // warp M offset (2 warps in M)
    const int wn = (wid & 3) * 64;    // warp N offset (4 warps in N)
    const long cRow = (long)blockIdx.y * BM;
    const long cCol = (long)blockIdx.x * BN;
    const int iters = K / BK;

    const float* Abase = A + cRow * (long)K;
    const float* Bbase = B + cCol * (long)K;

    auto load_stage = [&](int j, int s) {
        const float* Ag = Abase + (long)j * BK;
        const float* Bg = Bbase + (long)j * BK;
        float* Ast = sm + s * STAGE_F;
        float* Bst = Ast + A_TILE_F;
#pragma unroll
        for (int n = 0; n < 4; n++) {            // A: 128 rows x 8 16B-chunks
            int c = tid + n * 256;
            int row = c >> 3, ci = c & 7;
            cp16(Ast + row * LDS_ + ci * 4, Ag + (long)row * K + ci * 4);
        }
#pragma unroll
        for (int n = 0; n < 8; n++) {            // B: 256 rows x 8 16B-chunks
            int c = tid + n * 256;
            int row = c >> 3, ci = c & 7;
            cp16(Bst + row * LDS_ + ci * 4, Bg + (long)row * K + ci * 4);
        }
        asm volatile("cp.async.commit_group;" ::: "memory");
    };

    float acc[4][8][4];
#pragma unroll
    for (int mi = 0; mi < 4; mi++)
#pragma unroll
        for (int ni = 0; ni < 8; ni++)
#pragma unroll
            for (int r = 0; r < 4; r++) acc[mi][ni][r] = 0.f;

    // per-thread ldmatrix base byte offsets (within a stage)
    const uint32_t smb = smem_u32(sm);
    const uint32_t a_off = ((wm + (lane & 15)) * LDS_ + (lane >> 4) * 4) * 4;
    const uint32_t b_off = ((wn + (lane & 7)) * LDS_ + ((lane >> 3) & 1) * 4) * 4;

#pragma unroll
    for (int j = 0; j < STAGES - 1; j++) load_stage(j, j);

    for (int i = 0; i < iters; i++) {
        asm volatile("cp.async.wait_group %0;" :: "n"(STAGES - 2) : "memory");
        __syncthreads();

        const int jn = i + STAGES - 1;
        if (jn < iters) load_stage(jn, jn % STAGES);

        const uint32_t Au_b = smb + (uint32_t)((i % STAGES) * STAGE_F) * 4 + a_off;
        const uint32_t Bu_b = smb + (uint32_t)((i % STAGES) * STAGE_F + A_TILE_F) * 4 + b_off;

#pragma unroll
        for (int ks = 0; ks < 4; ks++) {
            const uint32_t kb = ks * 32;   // bytes: 8 tf32 per ks-step
            uint32_t a[4][4];
#pragma unroll
            for (int mi = 0; mi < 4; mi++)
                ldsm_x4(a[mi], Au_b + mi * (16 * LDS_ * 4) + kb);
            uint32_t b[8][2];
#pragma unroll
            for (int ni = 0; ni < 8; ni++)
                ldsm_x2(b[ni], Bu_b + ni * (8 * LDS_ * 4) + kb);
#pragma unroll
            for (int mi = 0; mi < 4; mi++)
#pragma unroll
                for (int ni = 0; ni < 8; ni++)
                    mma_tf32(acc[mi][ni], a[mi], b[ni]);
        }
    }

    // epilogue: direct register -> gmem
#pragma unroll
    for (int mi = 0; mi < 4; mi++) {
        const long rg = cRow + wm + mi * 16 + (lane >> 2);
        float rb0 = 0.f, rb1 = 0.f;
        if (ROWBIAS && HASBIAS) { rb0 = __ldg(&bias[rg]); rb1 = __ldg(&bias[rg + 8]); }
#pragma unroll
        for (int ni = 0; ni < 8; ni++) {
            const long cg = cCol + wn + ni * 8 + (lane & 3) * 2;
            float v0 = alpha * acc[mi][ni][0];
            float v1 = alpha * acc[mi][ni][1];
            float v2 = alpha * acc[mi][ni][2];
            float v3 = alpha * acc[mi][ni][3];
            if (HASBIAS) {
                if (ROWBIAS) { v0 += rb0; v1 += rb0; v2 += rb1; v3 += rb1; }
                else {
                    float cb0 = __ldg(&bias[cg]), cb1 = __ldg(&bias[cg + 1]);
                    v0 += cb0; v1 += cb1; v2 += cb0; v3 += cb1;
                }
            }
            if (ROUND_OUT) { v0 = tf32r(v0); v1 = tf32r(v1); v2 = tf32r(v2); v3 = tf32r(v3); }
            float2 lo; lo.x = v0; lo.y = v1;
            float2 hi; hi.x = v2; hi.y = v3;
            *(float2*)&C[rg * (long)N + cg] = lo;
            *(float2*)&C[(rg + 8) * (long)N + cg] = hi;
        }
    }
}

// ---------------- tf32 pre-round ----------------
__global__ void round_tf32_kernel(const float4* __restrict__ in, float4* __restrict__ out, int n4) {
    int i = blockIdx.x * blockDim.x + threadIdx.x;
    int st = gridDim.x * blockDim.x;
    for (; i < n4; i += st) {
        float4 v = in[i];
        v.x = tf32r(v.x); v.y = tf32r(v.y); v.z = tf32r(v.z); v.w = tf32r(v.w);
        out[i] = v;
    }
}

struct WPtrs { const float4* in[7]; float4* out[7]; };
__global__ void round_w_kernel(WPtrs wp, int n4) {
    const float4* in = wp.in[blockIdx.y];
    float4* out = wp.out[blockIdx.y];
    int i = blockIdx.x * blockDim.x + threadIdx.x;
    int st = gridDim.x * blockDim.x;
    for (; i < n4; i += st) {
        float4 v = in[i];
        v.x = tf32r(v.x); v.y = tf32r(v.y); v.z = tf32r(v.z); v.w = tf32r(v.w);
        out[i] = v;
    }
}

// ---------------- row softmax over NBANK=8192, in place, 2 buffers ----------------
__global__ __launch_bounds__(256) void softmax_kernel(float* __restrict__ P1, float* __restrict__ P2)
{
    int row = blockIdx.x;
    float* P = (row < NROIS) ? P1 : P2;
    if (row >= NROIS) row -= NROIS;
    const int tid = threadIdx.x;
    float4* rowp = (float4*)(P + (long)row * NBANK);

    float4 v[8];
    float lmax = -3.0e38f;
#pragma unroll
    for (int j = 0; j < 8; j++) {
        v[j] = rowp[tid + j * 256];
        lmax = fmaxf(lmax, fmaxf(fmaxf(v[j].x, v[j].y), fmaxf(v[j].z, v[j].w)));
    }
    __shared__ float red[256];
    red[tid] = lmax;
    __syncthreads();
    for (int s = 128; s > 0; s >>= 1) {
        if (tid < s) red[tid] = fmaxf(red[tid], red[tid + s]);
        __syncthreads();
    }
    const float m = red[0];
    __syncthreads();
    float lsum = 0.f;
#pragma unroll
    for (int j = 0; j < 8; j++) {
        v[j].x = __expf(v[j].x - m); v[j].y = __expf(v[j].y - m);
        v[j].z = __expf(v[j].z - m); v[j].w = __expf(v[j].w - m);
        lsum += v[j].x + v[j].y + v[j].z + v[j].w;
    }
    red[tid] = lsum;
    __syncthreads();
    for (int s = 128; s > 0; s >>= 1) {
        if (tid < s) red[tid] += red[tid + s];
        __syncthreads();
    }
    const float inv = 1.f / red[0];
#pragma unroll
    for (int j = 0; j < 8; j++) {
        v[j].x = tf32r(v[j].x * inv); v[j].y = tf32r(v[j].y * inv);
        v[j].z = tf32r(v[j].z * inv); v[j].w = tf32r(v[j].w * inv);
        rowp[tid + j * 256] = v[j];
    }
}

// ---------------- cpair = f1*f2 ; LayerNorm ; PReLU ; tf32-round ----------------
__global__ __launch_bounds__(256) void gate_ln_kernel(
    const float* __restrict__ f1, const float* __restrict__ f2,
    const float* __restrict__ lnw, const float* __restrict__ lnb,
    const float* __restrict__ prelu_a, float* __restrict__ x)
{
    const int row = blockIdx.x;
    const int tid = threadIdx.x;
    const float4 a = ((const float4*)(f1 + (long)row * LAT))[tid];
    const float4 b = ((const float4*)(f2 + (long)row * LAT))[tid];
    float4 c;
    c.x = a.x * b.x; c.y = a.y * b.y; c.z = a.z * b.z; c.w = a.w * b.w;

    __shared__ float red[256];
    red[tid] = c.x + c.y + c.z + c.w;
    __syncthreads();
    for (int s = 128; s > 0; s >>= 1) {
        if (tid < s) red[tid] += red[tid + s];
        __syncthreads();
    }
    const float mu = red[0] * (1.f / LAT);
    __syncthreads();
    float dx = c.x - mu, dy = c.y - mu, dz = c.z - mu, dw = c.w - mu;
    red[tid] = dx * dx + dy * dy + dz * dz + dw * dw;
    __syncthreads();
    for (int s = 128; s > 0; s >>= 1) {
        if (tid < s) red[tid] += red[tid + s];
        __syncthreads();
    }
    const float rstd = rsqrtf(red[0] * (1.f / LAT) + 1e-5f);
    const float slope = prelu_a[0];
    const float4 w = ((const float4*)lnw)[tid];
    const float4 bb = ((const float4*)lnb)[tid];
    float4 o;
    o.x = dx * rstd * w.x + bb.x;
    o.y = dy * rstd * w.y + bb.y;
    o.z = dz * rstd * w.z + bb.z;
    o.w = dw * rstd * w.w + bb.w;
    o.x = o.x >= 0.f ? o.x : slope * o.x;
    o.y = o.y >= 0.f ? o.y : slope * o.y;
    o.z = o.z >= 0.f ? o.z : slope * o.z;
    o.w = o.w >= 0.f ? o.w : slope * o.w;
    o.x = tf32r(o.x); o.y = tf32r(o.y); o.z = tf32r(o.z); o.w = tf32r(o.w);
    ((float4*)(x + (long)row * LAT))[tid] = o;
}

// ---------------- launch ----------------
extern "C" void kernel_launch(void* const* d_in, const int* in_sizes, int n_in,
                              void* d_out, int out_size)
{
    const float* feat = (const float*)d_in[0];
    const float* bank = (const float*)d_in[1];
    const float* Wc1 = (const float*)d_in[2];  const float* bc1 = (const float*)d_in[3];
    const float* Wc2 = (const float*)d_in[4];  const float* bc2 = (const float*)d_in[5];
    const float* Wc3 = (const float*)d_in[6];  const float* bc3 = (const float*)d_in[7];
    const float* Wd1 = (const float*)d_in[8];  const float* bd1 = (const float*)d_in[9];
    const float* Wd2 = (const float*)d_in[10]; const float* bd2 = (const float*)d_in[11];
    const float* Wd3 = (const float*)d_in[12]; const float* bd3 = (const float*)d_in[13];
    const float* lnw = (const float*)d_in[14]; const float* lnb = (const float*)d_in[15];
    const float* pra = (const float*)d_in[16];
    const float* Wffn = (const float*)d_in[17]; const float* bffn = (const float*)d_in[18];
    float* out = (float*)d_out;

    float *rfeat, *rbank, *rw, *q1, *q2, *k1, *k2, *v1t, *v2t, *p1, *p2, *f1, *f2, *x;
    cudaGetSymbolAddress((void**)&rfeat, g_rfeat);
    cudaGetSymbolAddress((void**)&rbank, g_rbank);
    cudaGetSymbolAddress((void**)&rw, g_rw);
    cudaGetSymbolAddress((void**)&q1, g_q1);
    cudaGetSymbolAddress((void**)&q2, g_q2);
    cudaGetSymbolAddress((void**)&k1, g_k1);
    cudaGetSymbolAddress((void**)&k2, g_k2);
    cudaGetSymbolAddress((void**)&v1t, g_v1t);
    cudaGetSymbolAddress((void**)&v2t, g_v2t);
    cudaGetSymbolAddress((void**)&p1, g_p1);
    cudaGetSymbolAddress((void**)&p2, g_p2);
    cudaGetSymbolAddress((void**)&f1, g_f1);
    cudaGetSymbolAddress((void**)&f2, g_f2);
    cudaGetSymbolAddress((void**)&x, g_x);
    const long WSZ = (long)LAT * DIMIN;
    float* rWc1 = rw + 0 * WSZ;  float* rWc2 = rw + 1 * WSZ;  float* rWc3 = rw + 2 * WSZ;
    float* rWd1 = rw + 3 * WSZ;  float* rWd2 = rw + 4 * WSZ;  float* rWd3 = rw + 5 * WSZ;
    float* rWffn = rw + 6 * WSZ;

    cudaFuncSetAttribute(gemm_mma<false, true,  true >, cudaFuncAttributeMaxDynamicSharedMemorySize, GSMEM);
    cudaFuncSetAttribute(gemm_mma<true,  true,  true >, cudaFuncAttributeMaxDynamicSharedMemorySize, GSMEM);
    cudaFuncSetAttribute(gemm_mma<false, false, false>, cudaFuncAttributeMaxDynamicSharedMemorySize, GSMEM);
    cudaFuncSetAttribute(gemm_mma<false, true,  false>, cudaFuncAttributeMaxDynamicSharedMemorySize, GSMEM);

    // pre-round all GEMM inputs to tf32 (rna): 3 launches
    round_tf32_kernel<<<2048, 256>>>((const float4*)feat, (float4*)rfeat, (int)((long)NROIS * QDIM_ / 4));
    round_tf32_kernel<<<4096, 256>>>((const float4*)bank, (float4*)rbank, (int)((long)NBANK * DIMIN / 4));
    {
        WPtrs wp;
        wp.in[0] = (const float4*)Wc1;  wp.out[0] = (float4*)rWc1;
        wp.in[1] = (const float4*)Wc2;  wp.out[1] = (float4*)rWc2;
        wp.in[2] = (const float4*)Wc3;  wp.out[2] = (float4*)rWc3;
        wp.in[3] = (const float4*)Wd1;  wp.out[3] = (float4*)rWd1;
        wp.in[4] = (const float4*)Wd2;  wp.out[4] = (float4*)rWd2;
        wp.in[5] = (const float4*)Wd3;  wp.out[5] = (float4*)rWd3;
        wp.in[6] = (const float4*)Wffn; wp.out[6] = (float4*)rWffn;
        round_w_kernel<<<dim3(512, 7), 256>>>(wp, (int)(WSZ / 4));
    }

    const dim3 blk(256);
    const float inv_sqrt = 0.03125f;  // 1/sqrt(1024)

    // merged projections
    {
        GB2 g; g.A[0] = rfeat; g.A[1] = rfeat; g.B[0] = rWc1; g.B[1] = rWd1;
        g.bias[0] = bc1; g.bias[1] = bd1; g.C[0] = q1; g.C[1] = q2;
        gemm_mma<false, true, true><<<dim3(LAT / BN, NROIS / BM, 2), blk, GSMEM>>>(g, NROIS, LAT, QDIM_, 1.f);
    }
    {
        GB2 g; g.A[0] = rbank; g.A[1] = rbank; g.B[0] = rWc2; g.B[1] = rWd2;
        g.bias[0] = bc2; g.bias[1] = bd2; g.C[0] = k1; g.C[1] = k2;
        gemm_mma<false, true, true><<<dim3(LAT / BN, NBANK / BM, 2), blk, GSMEM>>>(g, NBANK, LAT, DIMIN, 1.f);
    }
    {
        GB2 g; g.A[0] = rWc3; g.A[1] = rWd3; g.B[0] = rbank; g.B[1] = rbank;
        g.bias[0] = bc3; g.bias[1] = bd3; g.C[0] = v1t; g.C[1] = v2t;
        gemm_mma<true, true, true><<<dim3(NBANK / BN, LAT / BM, 2), blk, GSMEM>>>(g, LAT, NBANK, DIMIN, 1.f);
    }
    // merged QK
    {
        GB2 g; g.A[0] = q1; g.A[1] = q2; g.B[0] = k1; g.B[1] = k2;
        g.bias[0] = nullptr; g.bias[1] = nullptr; g.C[0] = p1; g.C[1] = p2;
        gemm_mma<false, false, false><<<dim3(NBANK / BN, NROIS / BM, 2), blk, GSMEM>>>(g, NROIS, NBANK, LAT, inv_sqrt);
    }
    // merged softmax
    softmax_kernel<<<2 * NROIS, blk>>>(p1, p2);
    // merged PV
    {
        GB2 g; g.A[0] = p1; g.A[1] = p2; g.B[0] = v1t; g.B[1] = v2t;
        g.bias[0] = nullptr; g.bias[1] = nullptr; g.C[0] = f1; g.C[1] = f2;
        gemm_mma<false, false, false><<<dim3(LAT / BN, NROIS / BM, 2), blk, GSMEM>>>(g, NROIS, LAT, NBANK, 1.f);
    }

    // gate + LayerNorm + PReLU (rounds x to tf32)
    gate_ln_kernel<<<NROIS, blk>>>(f1, f2, lnw, lnb, pra, x);

    // FFN (fp32 out)
    {
        GB2 g; g.A[0] = x; g.A[1] = x; g.B[0] = rWffn; g.B[1] = rWffn;
        g.bias[0] = bffn; g.bias[1] = bffn; g.C[0] = out; g.C[1] = out;
        gemm_mma<false, true, false><<<dim3(DIMIN / BN, NROIS / BM, 1), blk, GSMEM>>>(g, NROIS, DIMIN, LAT, 1.f);
    }
}

// round 7
// speedup vs baseline: 7.5029x; 1.8965x over previous
#include <cuda_runtime.h>
#include <cuda_fp16.h>
#include <cstdint>

#define NROIS 4096
#define NBANK 8192
#define DIMIN 2048
#define QDIM_ 2048
#define LAT 1024

// ---------------- scratch (device globals: allocation-free) ----------------
__device__ __half g_hfeat[NROIS * QDIM_];
__device__ __half g_hbank[NBANK * DIMIN];
__device__ __half g_hw[7][LAT * DIMIN];   // Wc1,Wc2,Wc3,Wd1,Wd2,Wd3,Wffn
__device__ __half g_q1[NROIS * LAT];
__device__ __half g_q2[NROIS * LAT];
__device__ __half g_k1[NBANK * LAT];
__device__ __half g_k2[NBANK * LAT];
__device__ __half g_v1t[LAT * NBANK];
__device__ __half g_v2t[LAT * NBANK];
__device__ __half g_p1[(long)NROIS * NBANK];
__device__ __half g_p2[(long)NROIS * NBANK];
__device__ __half g_f1[NROIS * LAT];
__device__ __half g_f2[NROIS * LAT];
__device__ __half g_x[NROIS * LAT];

// ---------------- helpers ----------------
__device__ __forceinline__ uint32_t smem_u32(const void* p) {
    uint32_t r;
    asm("{ .reg .u64 t; cvta.to.shared.u64 t, %1; cvt.u32.u64 %0, t; }" : "=r"(r) : "l"(p));
    return r;
}
__device__ __forceinline__ void cp16(const __half* smem_dst, const __half* gsrc) {
    uint32_t a = smem_u32(smem_dst);
    asm volatile("cp.async.cg.shared.global [%0], [%1], 16;" :: "r"(a), "l"(gsrc) : "memory");
}
__device__ __forceinline__ void mma_f16(float* d, const uint32_t* a, const uint32_t* b) {
    asm volatile(
        "mma.sync.aligned.m16n8k16.row.col.f32.f16.f16.f32 "
        "{%0,%1,%2,%3}, {%4,%5,%6,%7}, {%8,%9}, {%0,%1,%2,%3};"
        : "+f"(d[0]), "+f"(d[1]), "+f"(d[2]), "+f"(d[3])
        : "r"(a[0]), "r"(a[1]), "r"(a[2]), "r"(a[3]), "r"(b[0]), "r"(b[1]));
}
__device__ __forceinline__ void ldsm_x4(uint32_t* r, uint32_t addr) {
    asm volatile("ldmatrix.sync.aligned.m8n8.x4.shared.b16 {%0,%1,%2,%3}, [%4];"
        : "=r"(r[0]), "=r"(r[1]), "=r"(r[2]), "=r"(r[3]) : "r"(addr));
}
__device__ __forceinline__ void ldsm_x2(uint32_t* r, uint32_t addr) {
    asm volatile("ldmatrix.sync.aligned.m8n8.x2.shared.b16 {%0,%1}, [%2];"
        : "=r"(r[0]), "=r"(r[1]) : "r"(addr));
}

// ---------------- fp16-input GEMM: C = alpha * A[M,K] * B[N,K]^T (+bias) ----
// BM=128, BN=256, BK=64 halves; 8 warps (2x4), warp tile 64x64; fp32 accumulate.
// blockIdx.z selects one of 2 independent problems (same M,N,K).
#define BM 128
#define BN 256
#define BKH 64
#define STAGES 3
#define LDH 72                          // halves per smem row (144B, conflict-free, 16B-aligned)
#define A_TILE_H (128 * LDH)
#define B_TILE_H (256 * LDH)
#define STAGE_H (A_TILE_H + B_TILE_H)
#define GSMEM (STAGES * STAGE_H * 2)    // 165888 bytes -> 1 CTA/SM

struct GB2 {
    const __half* A[2];
    const __half* B[2];
    const float* bias[2];
    void* C[2];
};

template <bool ROWBIAS, bool HASBIAS, typename OutT>
__global__ __launch_bounds__(256, 1)
void gemm_mma(GB2 gb, int M, int N, int K, float alpha)
{
    extern __shared__ __half sm[];
    const int z = blockIdx.z;
    const __half* __restrict__ A = gb.A[z];
    const __half* __restrict__ B = gb.B[z];
    const float* __restrict__ bias = gb.bias[z];
    OutT* __restrict__ C = (OutT*)gb.C[z];

    const int tid = threadIdx.x;
    const int lane = tid & 31;
    const int wid = tid >> 5;
    const int wm = (wid >> 2) * 64;   // warp M offset (2 warps in M)
    const int wn = (wid & 3) * 64;    // warp N offset (4 warps in N)
    const long cRow = (long)blockIdx.y * BM;
    const long cCol = (long)blockIdx.x * BN;
    const int iters = K / BKH;

    const __half* Abase = A + cRow * (long)K;
    const __half* Bbase = B + cCol * (long)K;

    auto load_stage = [&](int j, int s) {
        const __half* Ag = Abase + (long)j * BKH;
        const __half* Bg = Bbase + (long)j * BKH;
        __half* Ast = sm + s * STAGE_H;
        __half* Bst = Ast + A_TILE_H;
#pragma unroll
        for (int n = 0; n < 4; n++) {            // A: 128 rows x 8 16B-chunks
            int c = tid + n * 256;
            int row = c >> 3, ci = c & 7;
            cp16(Ast + row * LDH + ci * 8, Ag + (long)row * K + ci * 8);
        }
#pragma unroll
        for (int n = 0; n < 8; n++) {            // B: 256 rows x 8 16B-chunks
            int c = tid + n * 256;
            int row = c >> 3, ci = c & 7;
            cp16(Bst + row * LDH + ci * 8, Bg + (long)row * K + ci * 8);
        }
        asm volatile("cp.async.commit_group;" ::: "memory");
    };

    float acc[4][8][4];
#pragma unroll
    for (int mi = 0; mi < 4; mi++)
#pragma unroll
        for (int ni = 0; ni < 8; ni++)
#pragma unroll
            for (int r = 0; r < 4; r++) acc[mi][ni][r] = 0.f;

    // per-thread ldmatrix base byte offsets (within a stage)
    const uint32_t smb = smem_u32(sm);
    const uint32_t a_off = ((wm + (lane & 15)) * LDH + (lane >> 4) * 8) * 2;
    const uint32_t b_off = ((wn + (lane & 7)) * LDH + ((lane >> 3) & 1) * 8) * 2;

#pragma unroll
    for (int j = 0; j < STAGES - 1; j++) load_stage(j, j);

    for (int i = 0; i < iters; i++) {
        asm volatile("cp.async.wait_group %0;" :: "n"(STAGES - 2) : "memory");
        __syncthreads();

        const int jn = i + STAGES - 1;
        if (jn < iters) load_stage(jn, jn % STAGES);

        const uint32_t Au_b = smb + (uint32_t)((i % STAGES) * STAGE_H) * 2 + a_off;
        const uint32_t Bu_b = smb + (uint32_t)((i % STAGES) * STAGE_H + A_TILE_H) * 2 + b_off;

#pragma unroll
        for (int ks = 0; ks < 4; ks++) {
            const uint32_t kb = ks * 32;   // 16 halves per k-chunk = 32 bytes
            uint32_t a[4][4];
#pragma unroll
            for (int mi = 0; mi < 4; mi++)
                ldsm_x4(a[mi], Au_b + mi * (16 * LDH * 2) + kb);
            uint32_t b[8][2];
#pragma unroll
            for (int ni = 0; ni < 8; ni++)
                ldsm_x2(b[ni], Bu_b + ni * (8 * LDH * 2) + kb);
#pragma unroll
            for (int mi = 0; mi < 4; mi++)
#pragma unroll
                for (int ni = 0; ni < 8; ni++)
                    mma_f16(acc[mi][ni], a[mi], b[ni]);
        }
    }

    // epilogue: direct register -> gmem
#pragma unroll
    for (int mi = 0; mi < 4; mi++) {
        const long rg = cRow + wm + mi * 16 + (lane >> 2);
        float rb0 = 0.f, rb1 = 0.f;
        if (ROWBIAS && HASBIAS) { rb0 = __ldg(&bias[rg]); rb1 = __ldg(&bias[rg + 8]); }
#pragma unroll
        for (int ni = 0; ni < 8; ni++) {
            const long cg = cCol + wn + ni * 8 + (lane & 3) * 2;
            float v0 = alpha * acc[mi][ni][0];
            float v1 = alpha * acc[mi][ni][1];
            float v2 = alpha * acc[mi][ni][2];
            float v3 = alpha * acc[mi][ni][3];
            if (HASBIAS) {
                if (ROWBIAS) { v0 += rb0; v1 += rb0; v2 += rb1; v3 += rb1; }
                else {
                    float cb0 = __ldg(&bias[cg]), cb1 = __ldg(&bias[cg + 1]);
                    v0 += cb0; v1 += cb1; v2 += cb0; v3 += cb1;
                }
            }
            if constexpr (sizeof(OutT) == 2) {
                *(__half2*)&C[rg * (long)N + cg] = __floats2half2_rn(v0, v1);
                *(__half2*)&C[(rg + 8) * (long)N + cg] = __floats2half2_rn(v2, v3);
            } else {
                float2 lo; lo.x = v0; lo.y = v1;
                float2 hi; hi.x = v2; hi.y = v3;
                *(float2*)&C[rg * (long)N + cg] = lo;
                *(float2*)&C[(rg + 8) * (long)N + cg] = hi;
            }
        }
    }
}

// ---------------- fp32 -> fp16 conversion ----------------
__global__ void f2h_kernel(const float4* __restrict__ in, __half2* __restrict__ out, int n4) {
    int i = blockIdx.x * blockDim.x + threadIdx.x;
    int st = gridDim.x * blockDim.x;
    for (; i < n4; i += st) {
        float4 v = in[i];
        out[2 * i + 0] = __floats2half2_rn(v.x, v.y);
        out[2 * i + 1] = __floats2half2_rn(v.z, v.w);
    }
}

struct WPtrs { const float4* in[7]; __half2* out[7]; };
__global__ void f2h_w_kernel(WPtrs wp, int n4) {
    const float4* in = wp.in[blockIdx.y];
    __half2* out = wp.out[blockIdx.y];
    int i = blockIdx.x * blockDim.x + threadIdx.x;
    int st = gridDim.x * blockDim.x;
    for (; i < n4; i += st) {
        float4 v = in[i];
        out[2 * i + 0] = __floats2half2_rn(v.x, v.y);
        out[2 * i + 1] = __floats2half2_rn(v.z, v.w);
    }
}

// ---------------- row softmax over NBANK=8192 fp16, in place, 2 buffers ----------------
__global__ __launch_bounds__(256) void softmax_kernel(__half* __restrict__ P1, __half* __restrict__ P2)
{
    int row = blockIdx.x;
    __half* P = (row < NROIS) ? P1 : P2;
    if (row >= NROIS) row -= NROIS;
    const int tid = threadIdx.x;
    uint4* rowp = (uint4*)(P + (long)row * NBANK);   // 1024 uint4 (8 halves each)

    uint4 u[4];
    float f[32];
    float lmax = -3.0e38f;
#pragma unroll
    for (int j = 0; j < 4; j++) {
        u[j] = rowp[tid + j * 256];
        const __half2* h2 = (const __half2*)&u[j];
#pragma unroll
        for (int q = 0; q < 4; q++) {
            float2 fv = __half22float2(h2[q]);
            f[j * 8 + q * 2 + 0] = fv.x;
            f[j * 8 + q * 2 + 1] = fv.y;
            lmax = fmaxf(lmax, fmaxf(fv.x, fv.y));
        }
    }

    __shared__ float red[256];
    red[tid] = lmax;
    __syncthreads();
    for (int s = 128; s > 0; s >>= 1) {
        if (tid < s) red[tid] = fmaxf(red[tid], red[tid + s]);
        __syncthreads();
    }
    const float m = red[0];
    __syncthreads();
    float lsum = 0.f;
#pragma unroll
    for (int j = 0; j < 32; j++) {
        f[j] = __expf(f[j] - m);
        lsum += f[j];
    }
    red[tid] = lsum;
    __syncthreads();
    for (int s = 128; s > 0; s >>= 1) {
        if (tid < s) red[tid] += red[tid + s];
        __syncthreads();
    }
    const float inv = 1.f / red[0];

#pragma unroll
    for (int j = 0; j < 4; j++) {
        __half2* h2 = (__half2*)&u[j];
#pragma unroll
        for (int q = 0; q < 4; q++)
            h2[q] = __floats2half2_rn(f[j * 8 + q * 2] * inv, f[j * 8 + q * 2 + 1] * inv);
        rowp[tid + j * 256] = u[j];
    }
}

// ---------------- cpair = f1*f2 ; LayerNorm ; PReLU ; fp16 out ----------------
__global__ __launch_bounds__(256) void gate_ln_kernel(
    const __half* __restrict__ f1, const __half* __restrict__ f2,
    const float* __restrict__ lnw, const float* __restrict__ lnb,
    const float* __restrict__ prelu_a, __half* __restrict__ x)
{
    const int row = blockIdx.x;
    const int tid = threadIdx.x;
    const uint2 ua = ((const uint2*)(f1 + (long)row * LAT))[tid];   // 4 halves
    const uint2 ub = ((const uint2*)(f2 + (long)row * LAT))[tid];
    float2 a01 = __half22float2(*(const __half2*)&ua.x);
    float2 a23 = __half22float2(*(const __half2*)&ua.y);
    float2 b01 = __half22float2(*(const __half2*)&ub.x);
    float2 b23 = __half22float2(*(const __half2*)&ub.y);
    float cx = a01.x * b01.x, cy = a01.y * b01.y;
    float cz = a23.x * b23.x, cw = a23.y * b23.y;

    __shared__ float red[256];
    red[tid] = cx + cy + cz + cw;
    __syncthreads();
    for (int s = 128; s > 0; s >>= 1) {
        if (tid < s) red[tid] += red[tid + s];
        __syncthreads();
    }
    const float mu = red[0] * (1.f / LAT);
    __syncthreads();
    float dx = cx - mu, dy = cy - mu, dz = cz - mu, dw = cw - mu;
    red[tid] = dx * dx + dy * dy + dz * dz + dw * dw;
    __syncthreads();
    for (int s = 128; s > 0; s >>= 1) {
        if (tid < s) red[tid] += red[tid + s];
        __syncthreads();
    }
    const float rstd = rsqrtf(red[0] * (1.f / LAT) + 1e-5f);
    const float slope = prelu_a[0];
    const float4 w = ((const float4*)lnw)[tid];
    const float4 bb = ((const float4*)lnb)[tid];
    float ox = dx * rstd * w.x + bb.x;
    float oy = dy * rstd * w.y + bb.y;
    float oz = dz * rstd * w.z + bb.z;
    float ow = dw * rstd * w.w + bb.w;
    ox = ox >= 0.f ? ox : slope * ox;
    oy = oy >= 0.f ? oy : slope * oy;
    oz = oz >= 0.f ? oz : slope * oz;
    ow = ow >= 0.f ? ow : slope * ow;
    uint2 o;
    *(__half2*)&o.x = __floats2half2_rn(ox, oy);
    *(__half2*)&o.y = __floats2half2_rn(oz, ow);
    ((uint2*)(x + (long)row * LAT))[tid] = o;
}

// ---------------- launch ----------------
extern "C" void kernel_launch(void* const* d_in, const int* in_sizes, int n_in,
                              void* d_out, int out_size)
{
    const float* feat = (const float*)d_in[0];
    const float* bank = (const float*)d_in[1];
    const float* Wc1 = (const float*)d_in[2];  const float* bc1 = (const float*)d_in[3];
    const float* Wc2 = (const float*)d_in[4];  const float* bc2 = (const float*)d_in[5];
    const float* Wc3 = (const float*)d_in[6];  const float* bc3 = (const float*)d_in[7];
    const float* Wd1 = (const float*)d_in[8];  const float* bd1 = (const float*)d_in[9];
    const float* Wd2 = (const float*)d_in[10]; const float* bd2 = (const float*)d_in[11];
    const float* Wd3 = (const float*)d_in[12]; const float* bd3 = (const float*)d_in[13];
    const float* lnw = (const float*)d_in[14]; const float* lnb = (const float*)d_in[15];
    const float* pra = (const float*)d_in[16];
    const float* Wffn = (const float*)d_in[17]; const float* bffn = (const float*)d_in[18];
    float* out = (float*)d_out;

    __half *hfeat, *hbank, *hw, *q1, *q2, *k1, *k2, *v1t, *v2t, *p1, *p2, *f1, *f2, *x;
    cudaGetSymbolAddress((void**)&hfeat, g_hfeat);
    cudaGetSymbolAddress((void**)&hbank, g_hbank);
    cudaGetSymbolAddress((void**)&hw, g_hw);
    cudaGetSymbolAddress((void**)&q1, g_q1);
    cudaGetSymbolAddress((void**)&q2, g_q2);
    cudaGetSymbolAddress((void**)&k1, g_k1);
    cudaGetSymbolAddress((void**)&k2, g_k2);
    cudaGetSymbolAddress((void**)&v1t, g_v1t);
    cudaGetSymbolAddress((void**)&v2t, g_v2t);
    cudaGetSymbolAddress((void**)&p1, g_p1);
    cudaGetSymbolAddress((void**)&p2, g_p2);
    cudaGetSymbolAddress((void**)&f1, g_f1);
    cudaGetSymbolAddress((void**)&f2, g_f2);
    cudaGetSymbolAddress((void**)&x, g_x);
    const long WSZ = (long)LAT * DIMIN;
    __half* hWc1 = hw + 0 * WSZ;  __half* hWc2 = hw + 1 * WSZ;  __half* hWc3 = hw + 2 * WSZ;
    __half* hWd1 = hw + 3 * WSZ;  __half* hWd2 = hw + 4 * WSZ;  __half* hWd3 = hw + 5 * WSZ;
    __half* hWffn = hw + 6 * WSZ;

    cudaFuncSetAttribute(gemm_mma<false, true,  __half>, cudaFuncAttributeMaxDynamicSharedMemorySize, GSMEM);
    cudaFuncSetAttribute(gemm_mma<true,  true,  __half>, cudaFuncAttributeMaxDynamicSharedMemorySize, GSMEM);
    cudaFuncSetAttribute(gemm_mma<false, false, __half>, cudaFuncAttributeMaxDynamicSharedMemorySize, GSMEM);
    cudaFuncSetAttribute(gemm_mma<false, true,  float >, cudaFuncAttributeMaxDynamicSharedMemorySize, GSMEM);

    // convert all GEMM inputs to fp16: 3 launches
    f2h_kernel<<<2048, 256>>>((const float4*)feat, (__half2*)hfeat, (int)((long)NROIS * QDIM_ / 4));
    f2h_kernel<<<4096, 256>>>((const float4*)bank, (__half2*)hbank, (int)((long)NBANK * DIMIN / 4));
    {
        WPtrs wp;
        wp.in[0] = (const float4*)Wc1;  wp.out[0] = (__half2*)hWc1;
        wp.in[1] = (const float4*)Wc2;  wp.out[1] = (__half2*)hWc2;
        wp.in[2] = (const float4*)Wc3;  wp.out[2] = (__half2*)hWc3;
        wp.in[3] = (const float4*)Wd1;  wp.out[3] = (__half2*)hWd1;
        wp.in[4] = (const float4*)Wd2;  wp.out[4] = (__half2*)hWd2;
        wp.in[5] = (const float4*)Wd3;  wp.out[5] = (__half2*)hWd3;
        wp.in[6] = (const float4*)Wffn; wp.out[6] = (__half2*)hWffn;
        f2h_w_kernel<<<dim3(512, 7), 256>>>(wp, (int)(WSZ / 4));
    }

    const dim3 blk(256);
    const float inv_sqrt = 0.03125f;  // 1/sqrt(1024)

    // merged projections
    {
        GB2 g; g.A[0] = hfeat; g.A[1] = hfeat; g.B[0] = hWc1; g.B[1] = hWd1;
        g.bias[0] = bc1; g.bias[1] = bd1; g.C[0] = q1; g.C[1] = q2;
        gemm_mma<false, true, __half><<<dim3(LAT / BN, NROIS / BM, 2), blk, GSMEM>>>(g, NROIS, LAT, QDIM_, 1.f);
    }
    {
        GB2 g; g.A[0] = hbank; g.A[1] = hbank; g.B[0] = hWc2; g.B[1] = hWd2;
        g.bias[0] = bc2; g.bias[1] = bd2; g.C[0] = k1; g.C[1] = k2;
        gemm_mma<false, true, __half><<<dim3(LAT / BN, NBANK / BM, 2), blk, GSMEM>>>(g, NBANK, LAT, DIMIN, 1.f);
    }
    {
        GB2 g; g.A[0] = hWc3; g.A[1] = hWd3; g.B[0] = hbank; g.B[1] = hbank;
        g.bias[0] = bc3; g.bias[1] = bd3; g.C[0] = v1t; g.C[1] = v2t;
        gemm_mma<true, true, __half><<<dim3(NBANK / BN, LAT / BM, 2), blk, GSMEM>>>(g, LAT, NBANK, DIMIN, 1.f);
    }
    // merged QK
    {
        GB2 g; g.A[0] = q1; g.A[1] = q2; g.B[0] = k1; g.B[1] = k2;
        g.bias[0] = nullptr; g.bias[1] = nullptr; g.C[0] = p1; g.C[1] = p2;
        gemm_mma<false, false, __half><<<dim3(NBANK / BN, NROIS / BM, 2), blk, GSMEM>>>(g, NROIS, NBANK, LAT, inv_sqrt);
    }
    // merged softmax
    softmax_kernel<<<2 * NROIS, blk>>>(p1, p2);
    // merged PV
    {
        GB2 g; g.A[0] = p1; g.A[1] = p2; g.B[0] = v1t; g.B[1] = v2t;
        g.bias[0] = nullptr; g.bias[1] = nullptr; g.C[0] = f1; g.C[1] = f2;
        gemm_mma<false, false, __half><<<dim3(LAT / BN, NROIS / BM, 2), blk, GSMEM>>>(g, NROIS, LAT, NBANK, 1.f);
    }

    // gate + LayerNorm + PReLU (fp16 out)
    gate_ln_kernel<<<NROIS, blk>>>(f1, f2, lnw, lnb, pra, x);

    // FFN (fp32 out)
    {
        GB2 g; g.A[0] = x; g.A[1] = x; g.B[0] = hWffn; g.B[1] = hWffn;
        g.bias[0] = bffn; g.bias[1] = bffn; g.C[0] = out; g.C[1] = out;
        gemm_mma<false, true, float><<<dim3(DIMIN / BN, NROIS / BM, 1), blk, GSMEM>>>(g, NROIS, DIMIN, LAT, 1.f);
    }
}

// round 8
// speedup vs baseline: 7.7774x; 1.0366x over previous
#include <cuda_runtime.h>
#include <cuda_fp16.h>
#include <cstdint>

#define NROIS 4096
#define NBANK 8192
#define DIMIN 2048
#define QDIM_ 2048
#define LAT 1024

// ---------------- scratch (device globals: allocation-free) ----------------
__device__ __half g_hfeat[NROIS * QDIM_];
__device__ __half g_hbank[NBANK * DIMIN];
__device__ __half g_hw[7][LAT * DIMIN];   // Wc1,Wc2,Wc3,Wd1,Wd2,Wd3,Wffn
__device__ __half g_q1[NROIS * LAT];
__device__ __half g_q2[NROIS * LAT];
__device__ __half g_k1[NBANK * LAT];
__device__ __half g_k2[NBANK * LAT];
__device__ __half g_v1t[LAT * NBANK];
__device__ __half g_v2t[LAT * NBANK];
__device__ __half g_p1[(long)NROIS * NBANK];
__device__ __half g_p2[(long)NROIS * NBANK];
__device__ __half g_f1[NROIS * LAT];
__device__ __half g_f2[NROIS * LAT];
__device__ __half g_x[NROIS * LAT];

// ---------------- helpers ----------------
__device__ __forceinline__ uint32_t smem_u32(const void* p) {
    uint32_t r;
    asm("{ .reg .u64 t; cvta.to.shared.u64 t, %1; cvt.u32.u64 %0, t; }" : "=r"(r) : "l"(p));
    return r;
}
__device__ __forceinline__ void cp16(const __half* smem_dst, const __half* gsrc) {
    uint32_t a = smem_u32(smem_dst);
    asm volatile("cp.async.cg.shared.global [%0], [%1], 16;" :: "r"(a), "l"(gsrc) : "memory");
}
__device__ __forceinline__ void mma_f16(float* d, const uint32_t* a, const uint32_t* b) {
    asm volatile(
        "mma.sync.aligned.m16n8k16.row.col.f32.f16.f16.f32 "
        "{%0,%1,%2,%3}, {%4,%5,%6,%7}, {%8,%9}, {%0,%1,%2,%3};"
        : "+f"(d[0]), "+f"(d[1]), "+f"(d[2]), "+f"(d[3])
        : "r"(a[0]), "r"(a[1]), "r"(a[2]), "r"(a[3]), "r"(b[0]), "r"(b[1]));
}
__device__ __forceinline__ void ldsm_x4(uint32_t* r, uint32_t addr) {
    asm volatile("ldmatrix.sync.aligned.m8n8.x4.shared.b16 {%0,%1,%2,%3}, [%4];"
        : "=r"(r[0]), "=r"(r[1]), "=r"(r[2]), "=r"(r[3]) : "r"(addr));
}
__device__ __forceinline__ void ldsm_x2(uint32_t* r, uint32_t addr) {
    asm volatile("ldmatrix.sync.aligned.m8n8.x2.shared.b16 {%0,%1}, [%2];"
        : "=r"(r[0]), "=r"(r[1]) : "r"(addr));
}

// ---------------- fp16-input multi-problem GEMM ----------------
// C = alpha * A[M,K] * B[N,K]^T (+bias); BM=128, BN=256, BK=64 halves;
// 8 warps (2x4), warp tile 64x64; fp32 accumulate.
// One launch serves up to 6 problems; linear blockIdx -> (problem, tile).
#define BM 128
#define BN 256
#define BKH 64
#define STAGES 3
#define LDH 72                          // halves per smem row (144B, conflict-free)
#define A_TILE_H (128 * LDH)
#define B_TILE_H (256 * LDH)
#define STAGE_H (A_TILE_H + B_TILE_H)
#define GSMEM (STAGES * STAGE_H * 2)    // 165888 bytes -> 1 CTA/SM

struct Prob {
    const __half* A;
    const __half* B;
    const float* bias;
    void* C;
    int M, N, K;
    int tx;          // tiles in N direction
    int bias_mode;   // 0 none, 1 column bias, 2 row bias
    float alpha;
};
struct MultiP {
    Prob p[6];
    int start[7];    // prefix tile offsets; start[np..6] = total (sentinel)
};

template <typename OutT>
__global__ __launch_bounds__(256, 1)
void gemm_multi(MultiP mu)
{
    extern __shared__ __half sm[];
    // map linear block -> (problem, tile)
    int j = 0;
    const int bid = blockIdx.x;
    while (bid >= mu.start[j + 1]) j++;
    const Prob pr = mu.p[j];
    const int t = bid - mu.start[j];
    const __half* __restrict__ A = pr.A;
    const __half* __restrict__ B = pr.B;
    const float* __restrict__ bias = pr.bias;
    OutT* __restrict__ C = (OutT*)pr.C;
    const int N = pr.N;
    const int K = pr.K;
    const float alpha = pr.alpha;
    const long cRow = (long)(t / pr.tx) * BM;
    const long cCol = (long)(t % pr.tx) * BN;

    const int tid = threadIdx.x;
    const int lane = tid & 31;
    const int wid = tid >> 5;
    const int wm = (wid >> 2) * 64;   // warp M offset (2 warps in M)
    const int wn = (wid & 3) * 64;    // warp N offset (4 warps in N)
    const int iters = K / BKH;

    const __half* Abase = A + cRow * (long)K;
    const __half* Bbase = B + cCol * (long)K;

    auto load_stage = [&](int jj, int s) {
        const __half* Ag = Abase + (long)jj * BKH;
        const __half* Bg = Bbase + (long)jj * BKH;
        __half* Ast = sm + s * STAGE_H;
        __half* Bst = Ast + A_TILE_H;
#pragma unroll
        for (int n = 0; n < 4; n++) {            // A: 128 rows x 8 16B-chunks
            int c = tid + n * 256;
            int row = c >> 3, ci = c & 7;
            cp16(Ast + row * LDH + ci * 8, Ag + (long)row * K + ci * 8);
        }
#pragma unroll
        for (int n = 0; n < 8; n++) {            // B: 256 rows x 8 16B-chunks
            int c = tid + n * 256;
            int row = c >> 3, ci = c & 7;
            cp16(Bst + row * LDH + ci * 8, Bg + (long)row * K + ci * 8);
        }
        asm volatile("cp.async.commit_group;" ::: "memory");
    };

    float acc[4][8][4];
#pragma unroll
    for (int mi = 0; mi < 4; mi++)
#pragma unroll
        for (int ni = 0; ni < 8; ni++)
#pragma unroll
            for (int r = 0; r < 4; r++) acc[mi][ni][r] = 0.f;

    const uint32_t smb = smem_u32(sm);
    const uint32_t a_off = ((wm + (lane & 15)) * LDH + (lane >> 4) * 8) * 2;
    const uint32_t b_off = ((wn + (lane & 7)) * LDH + ((lane >> 3) & 1) * 8) * 2;

#pragma unroll
    for (int jj = 0; jj < STAGES - 1; jj++) load_stage(jj, jj);

    for (int i = 0; i < iters; i++) {
        if (i == iters - 1)
            asm volatile("cp.async.wait_group 0;" ::: "memory");
        else
            asm volatile("cp.async.wait_group 1;" ::: "memory");
        __syncthreads();

        const int jn = i + STAGES - 1;
        if (jn < iters) load_stage(jn, jn % STAGES);

        const uint32_t Au_b = smb + (uint32_t)((i % STAGES) * STAGE_H) * 2 + a_off;
        const uint32_t Bu_b = smb + (uint32_t)((i % STAGES) * STAGE_H + A_TILE_H) * 2 + b_off;

#pragma unroll
        for (int ks = 0; ks < 4; ks++) {
            const uint32_t kb = ks * 32;   // 16 halves per k-chunk = 32 bytes
            uint32_t a[4][4];
#pragma unroll
            for (int mi = 0; mi < 4; mi++)
                ldsm_x4(a[mi], Au_b + mi * (16 * LDH * 2) + kb);
            uint32_t b[8][2];
#pragma unroll
            for (int ni = 0; ni < 8; ni++)
                ldsm_x2(b[ni], Bu_b + ni * (8 * LDH * 2) + kb);
#pragma unroll
            for (int mi = 0; mi < 4; mi++)
#pragma unroll
                for (int ni = 0; ni < 8; ni++)
                    mma_f16(acc[mi][ni], a[mi], b[ni]);
        }
    }

    // epilogue: direct register -> gmem
#pragma unroll
    for (int mi = 0; mi < 4; mi++) {
        const long rg = cRow + wm + mi * 16 + (lane >> 2);
        float rb0 = 0.f, rb1 = 0.f;
        if (pr.bias_mode == 2) { rb0 = __ldg(&bias[rg]); rb1 = __ldg(&bias[rg + 8]); }
#pragma unroll
        for (int ni = 0; ni < 8; ni++) {
            const long cg = cCol + wn + ni * 8 + (lane & 3) * 2;
            float v0 = alpha * acc[mi][ni][0];
            float v1 = alpha * acc[mi][ni][1];
            float v2 = alpha * acc[mi][ni][2];
            float v3 = alpha * acc[mi][ni][3];
            if (pr.bias_mode == 1) {
                float cb0 = __ldg(&bias[cg]), cb1 = __ldg(&bias[cg + 1]);
                v0 += cb0; v1 += cb1; v2 += cb0; v3 += cb1;
            } else if (pr.bias_mode == 2) {
                v0 += rb0; v1 += rb0; v2 += rb1; v3 += rb1;
            }
            if constexpr (sizeof(OutT) == 2) {
                *(__half2*)&C[rg * (long)N + cg] = __floats2half2_rn(v0, v1);
                *(__half2*)&C[(rg + 8) * (long)N + cg] = __floats2half2_rn(v2, v3);
            } else {
                float2 lo; lo.x = v0; lo.y = v1;
                float2 hi; hi.x = v2; hi.y = v3;
                *(float2*)&C[rg * (long)N + cg] = lo;
                *(float2*)&C[(rg + 8) * (long)N + cg] = hi;
            }
        }
    }
}

// ---------------- fp32 -> fp16 conversion ----------------
__global__ void f2h_kernel(const float4* __restrict__ in, __half2* __restrict__ out, int n4) {
    int i = blockIdx.x * blockDim.x + threadIdx.x;
    int st = gridDim.x * blockDim.x;
    for (; i < n4; i += st) {
        float4 v = in[i];
        out[2 * i + 0] = __floats2half2_rn(v.x, v.y);
        out[2 * i + 1] = __floats2half2_rn(v.z, v.w);
    }
}

struct WPtrs { const float4* in[7]; __half2* out[7]; };
__global__ void f2h_w_kernel(WPtrs wp, int n4) {
    const float4* in = wp.in[blockIdx.y];
    __half2* out = wp.out[blockIdx.y];
    int i = blockIdx.x * blockDim.x + threadIdx.x;
    int st = gridDim.x * blockDim.x;
    for (; i < n4; i += st) {
        float4 v = in[i];
        out[2 * i + 0] = __floats2half2_rn(v.x, v.y);
        out[2 * i + 1] = __floats2half2_rn(v.z, v.w);
    }
}

// ---------------- row softmax over NBANK=8192 fp16, in place ----------------
__global__ __launch_bounds__(256) void softmax_kernel(__half* __restrict__ P)
{
    const int row = blockIdx.x;
    const int tid = threadIdx.x;
    uint4* rowp = (uint4*)(P + (long)row * NBANK);   // 1024 uint4 (8 halves each)

    uint4 u[4];
    float f[32];
    float lmax = -3.0e38f;
#pragma unroll
    for (int j = 0; j < 4; j++) {
        u[j] = rowp[tid + j * 256];
        const __half2* h2 = (const __half2*)&u[j];
#pragma unroll
        for (int q = 0; q < 4; q++) {
            float2 fv = __half22float2(h2[q]);
            f[j * 8 + q * 2 + 0] = fv.x;
            f[j * 8 + q * 2 + 1] = fv.y;
            lmax = fmaxf(lmax, fmaxf(fv.x, fv.y));
        }
    }

    __shared__ float red[256];
    red[tid] = lmax;
    __syncthreads();
    for (int s = 128; s > 0; s >>= 1) {
        if (tid < s) red[tid] = fmaxf(red[tid], red[tid + s]);
        __syncthreads();
    }
    const float m = red[0];
    __syncthreads();
    float lsum = 0.f;
#pragma unroll
    for (int j = 0; j < 32; j++) {
        f[j] = __expf(f[j] - m);
        lsum += f[j];
    }
    red[tid] = lsum;
    __syncthreads();
    for (int s = 128; s > 0; s >>= 1) {
        if (tid < s) red[tid] += red[tid + s];
        __syncthreads();
    }
    const float inv = 1.f / red[0];

#pragma unroll
    for (int j = 0; j < 4; j++) {
        __half2* h2 = (__half2*)&u[j];
#pragma unroll
        for (int q = 0; q < 4; q++)
            h2[q] = __floats2half2_rn(f[j * 8 + q * 2] * inv, f[j * 8 + q * 2 + 1] * inv);
        rowp[tid + j * 256] = u[j];
    }
}

// ---------------- cpair = f1*f2 ; LayerNorm ; PReLU ; fp16 out ----------------
__global__ __launch_bounds__(256) void gate_ln_kernel(
    const __half* __restrict__ f1, const __half* __restrict__ f2,
    const float* __restrict__ lnw, const float* __restrict__ lnb,
    const float* __restrict__ prelu_a, __half* __restrict__ x)
{
    const int row = blockIdx.x;
    const int tid = threadIdx.x;
    const uint2 ua = ((const uint2*)(f1 + (long)row * LAT))[tid];   // 4 halves
    const uint2 ub = ((const uint2*)(f2 + (long)row * LAT))[tid];
    float2 a01 = __half22float2(*(const __half2*)&ua.x);
    float2 a23 = __half22float2(*(const __half2*)&ua.y);
    float2 b01 = __half22float2(*(const __half2*)&ub.x);
    float2 b23 = __half22float2(*(const __half2*)&ub.y);
    float cx = a01.x * b01.x, cy = a01.y * b01.y;
    float cz = a23.x * b23.x, cw = a23.y * b23.y;

    __shared__ float red[256];
    red[tid] = cx + cy + cz + cw;
    __syncthreads();
    for (int s = 128; s > 0; s >>= 1) {
        if (tid < s) red[tid] += red[tid + s];
        __syncthreads();
    }
    const float mu = red[0] * (1.f / LAT);
    __syncthreads();
    float dx = cx - mu, dy = cy - mu, dz = cz - mu, dw = cw - mu;
    red[tid] = dx * dx + dy * dy + dz * dz + dw * dw;
    __syncthreads();
    for (int s = 128; s > 0; s >>= 1) {
        if (tid < s) red[tid] += red[tid + s];
        __syncthreads();
    }
    const float rstd = rsqrtf(red[0] * (1.f / LAT) + 1e-5f);
    const float slope = prelu_a[0];
    const float4 w = ((const float4*)lnw)[tid];
    const float4 bb = ((const float4*)lnb)[tid];
    float ox = dx * rstd * w.x + bb.x;
    float oy = dy * rstd * w.y + bb.y;
    float oz = dz * rstd * w.z + bb.z;
    float ow = dw * rstd * w.w + bb.w;
    ox = ox >= 0.f ? ox : slope * ox;
    oy = oy >= 0.f ? oy : slope * oy;
    oz = oz >= 0.f ? oz : slope * oz;
    ow = ow >= 0.f ? ow : slope * ow;
    uint2 o;
    *(__half2*)&o.x = __floats2half2_rn(ox, oy);
    *(__half2*)&o.y = __floats2half2_rn(oz, ow);
    ((uint2*)(x + (long)row * LAT))[tid] = o;
}

// ---------------- launch ----------------
static inline Prob mkprob(const __half* A, const __half* B, const float* bias, void* C,
                          int M, int N, int K, int bias_mode, float alpha) {
    Prob p; p.A = A; p.B = B; p.bias = bias; p.C = C;
    p.M = M; p.N = N; p.K = K; p.tx = N / BN; p.bias_mode = bias_mode; p.alpha = alpha;
    return p;
}

extern "C" void kernel_launch(void* const* d_in, const int* in_sizes, int n_in,
                              void* d_out, int out_size)
{
    const float* feat = (const float*)d_in[0];
    const float* bank = (const float*)d_in[1];
    const float* Wc1 = (const float*)d_in[2];  const float* bc1 = (const float*)d_in[3];
    const float* Wc2 = (const float*)d_in[4];  const float* bc2 = (const float*)d_in[5];
    const float* Wc3 = (const float*)d_in[6];  const float* bc3 = (const float*)d_in[7];
    const float* Wd1 = (const float*)d_in[8];  const float* bd1 = (const float*)d_in[9];
    const float* Wd2 = (const float*)d_in[10]; const float* bd2 = (const float*)d_in[11];
    const float* Wd3 = (const float*)d_in[12]; const float* bd3 = (const float*)d_in[13];
    const float* lnw = (const float*)d_in[14]; const float* lnb = (const float*)d_in[15];
    const float* pra = (const float*)d_in[16];
    const float* Wffn = (const float*)d_in[17]; const float* bffn = (const float*)d_in[18];
    float* out = (float*)d_out;

    __half *hfeat, *hbank, *hw, *q1, *q2, *k1, *k2, *v1t, *v2t, *p1, *p2, *f1, *f2, *x;
    cudaGetSymbolAddress((void**)&hfeat, g_hfeat);
    cudaGetSymbolAddress((void**)&hbank, g_hbank);
    cudaGetSymbolAddress((void**)&hw, g_hw);
    cudaGetSymbolAddress((void**)&q1, g_q1);
    cudaGetSymbolAddress((void**)&q2, g_q2);
    cudaGetSymbolAddress((void**)&k1, g_k1);
    cudaGetSymbolAddress((void**)&k2, g_k2);
    cudaGetSymbolAddress((void**)&v1t, g_v1t);
    cudaGetSymbolAddress((void**)&v2t, g_v2t);
    cudaGetSymbolAddress((void**)&p1, g_p1);
    cudaGetSymbolAddress((void**)&p2, g_p2);
    cudaGetSymbolAddress((void**)&f1, g_f1);
    cudaGetSymbolAddress((void**)&f2, g_f2);
    cudaGetSymbolAddress((void**)&x, g_x);
    const long WSZ = (long)LAT * DIMIN;
    __half* hWc1 = hw + 0 * WSZ;  __half* hWc2 = hw + 1 * WSZ;  __half* hWc3 = hw + 2 * WSZ;
    __half* hWd1 = hw + 3 * WSZ;  __half* hWd2 = hw + 4 * WSZ;  __half* hWd3 = hw + 5 * WSZ;
    __half* hWffn = hw + 6 * WSZ;

    cudaFuncSetAttribute(gemm_multi<__half>, cudaFuncAttributeMaxDynamicSharedMemorySize, GSMEM);
    cudaFuncSetAttribute(gemm_multi<float>,  cudaFuncAttributeMaxDynamicSharedMemorySize, GSMEM);

    // convert all GEMM inputs to fp16
    f2h_kernel<<<2048, 256>>>((const float4*)feat, (__half2*)hfeat, (int)((long)NROIS * QDIM_ / 4));
    f2h_kernel<<<4096, 256>>>((const float4*)bank, (__half2*)hbank, (int)((long)NBANK * DIMIN / 4));
    {
        WPtrs wp;
        wp.in[0] = (const float4*)Wc1;  wp.out[0] = (__half2*)hWc1;
        wp.in[1] = (const float4*)Wc2;  wp.out[1] = (__half2*)hWc2;
        wp.in[2] = (const float4*)Wc3;  wp.out[2] = (__half2*)hWc3;
        wp.in[3] = (const float4*)Wd1;  wp.out[3] = (__half2*)hWd1;
        wp.in[4] = (const float4*)Wd2;  wp.out[4] = (__half2*)hWd2;
        wp.in[5] = (const float4*)Wd3;  wp.out[5] = (__half2*)hWd3;
        wp.in[6] = (const float4*)Wffn; wp.out[6] = (__half2*)hWffn;
        f2h_w_kernel<<<dim3(512, 7), 256>>>(wp, (int)(WSZ / 4));
    }

    const dim3 blk(256);
    const float inv_sqrt = 0.03125f;  // 1/sqrt(1024)

    // Phase B: all 6 projections in one launch (uniform K=2048 tiles)
    {
        MultiP mu;
        mu.p[0] = mkprob(hfeat, hWc1, bc1, q1, NROIS, LAT, QDIM_, 1, 1.f);   // 128 tiles
        mu.p[1] = mkprob(hfeat, hWd1, bd1, q2, NROIS, LAT, QDIM_, 1, 1.f);   // 128
        mu.p[2] = mkprob(hbank, hWc2, bc2, k1, NBANK, LAT, DIMIN, 1, 1.f);   // 256
        mu.p[3] = mkprob(hbank, hWd2, bd2, k2, NBANK, LAT, DIMIN, 1, 1.f);   // 256
        mu.p[4] = mkprob(hWc3, hbank, bc3, v1t, LAT, NBANK, DIMIN, 2, 1.f);  // 256 (row bias)
        mu.p[5] = mkprob(hWd3, hbank, bd3, v2t, LAT, NBANK, DIMIN, 2, 1.f);  // 256
        int st[7] = {0, 128, 256, 512, 768, 1024, 1280};
        for (int i = 0; i < 7; i++) mu.start[i] = st[i];
        gemm_multi<__half><<<1280, blk, GSMEM>>>(mu);
    }
    // Phase C: QK1
    {
        MultiP mu;
        mu.p[0] = mkprob(q1, k1, nullptr, p1, NROIS, NBANK, LAT, 0, inv_sqrt);  // 1024 tiles
        mu.start[0] = 0;
        for (int i = 1; i < 7; i++) mu.start[i] = 1024;
        gemm_multi<__half><<<1024, blk, GSMEM>>>(mu);
    }
    // Phase D: softmax branch 1
    softmax_kernel<<<NROIS, blk>>>(p1);
    // Phase E: PV1 (long tiles first) + QK2 in one launch
    {
        MultiP mu;
        mu.p[0] = mkprob(p1, v1t, nullptr, f1, NROIS, LAT, NBANK, 0, 1.f);      // 128 long tiles
        mu.p[1] = mkprob(q2, k2, nullptr, p2, NROIS, NBANK, LAT, 0, inv_sqrt);  // 1024 tiles
        mu.start[0] = 0; mu.start[1] = 128;
        for (int i = 2; i < 7; i++) mu.start[i] = 1152;
        gemm_multi<__half><<<1152, blk, GSMEM>>>(mu);
    }
    // Phase F: softmax branch 2
    softmax_kernel<<<NROIS, blk>>>(p2);
    // Phase G: PV2
    {
        MultiP mu;
        mu.p[0] = mkprob(p2, v2t, nullptr, f2, NROIS, LAT, NBANK, 0, 1.f);  // 128 tiles
        mu.start[0] = 0;
        for (int i = 1; i < 7; i++) mu.start[i] = 128;
        gemm_multi<__half><<<128, blk, GSMEM>>>(mu);
    }
    // Phase H: gate + LayerNorm + PReLU
    gate_ln_kernel<<<NROIS, blk>>>(f1, f2, lnw, lnb, pra, x);
    // Phase I: FFN (fp32 out)
    {
        MultiP mu;
        mu.p[0] = mkprob(x, hWffn, bffn, out, NROIS, DIMIN, LAT, 1, 1.f);  // 256 tiles
        mu.start[0] = 0;
        for (int i = 1; i < 7; i++) mu.start[i] = 256;
        gemm_multi<float><<<256, blk, GSMEM>>>(mu);
    }
}

// round 9
// speedup vs baseline: 7.8492x; 1.0092x over previous
#include <cuda_runtime.h>
#include <cuda_fp16.h>
#include <cstdint>

#define NROIS 4096
#define NBANK 8192
#define DIMIN 2048
#define QDIM_ 2048
#define LAT 1024

// ---------------- scratch (device globals: allocation-free) ----------------
__device__ __half g_hfeat[NROIS * QDIM_];
__device__ __half g_hbank[NBANK * DIMIN];
__device__ __half g_hw[7][LAT * DIMIN];   // Wc1,Wc2,Wc3,Wd1,Wd2,Wd3,Wffn
__device__ __half g_q1[NROIS * LAT];
__device__ __half g_q2[NROIS * LAT];
__device__ __half g_k1[NBANK * LAT];
__device__ __half g_k2[NBANK * LAT];
__device__ __half g_v1t[LAT * NBANK];
__device__ __half g_v2t[LAT * NBANK];
__device__ __half g_p1[(long)NROIS * NBANK];
__device__ __half g_p2[(long)NROIS * NBANK];
__device__ float g_ps1[NROIS * 128];      // per-row partial exp-sums, branch 1
__device__ float g_ps2[NROIS * 128];      // branch 2
__device__ __half g_f1[NROIS * LAT];
__device__ __half g_f2[NROIS * LAT];
__device__ __half g_x[NROIS * LAT];

// ---------------- helpers ----------------
__device__ __forceinline__ uint32_t smem_u32(const void* p) {
    uint32_t r;
    asm("{ .reg .u64 t; cvta.to.shared.u64 t, %1; cvt.u32.u64 %0, t; }" : "=r"(r) : "l"(p));
    return r;
}
__device__ __forceinline__ void cp16(const __half* smem_dst, const __half* gsrc) {
    uint32_t a = smem_u32(smem_dst);
    asm volatile("cp.async.cg.shared.global [%0], [%1], 16;" :: "r"(a), "l"(gsrc) : "memory");
}
__device__ __forceinline__ void mma_f16(float* d, const uint32_t* a, const uint32_t* b) {
    asm volatile(
        "mma.sync.aligned.m16n8k16.row.col.f32.f16.f16.f32 "
        "{%0,%1,%2,%3}, {%4,%5,%6,%7}, {%8,%9}, {%0,%1,%2,%3};"
        : "+f"(d[0]), "+f"(d[1]), "+f"(d[2]), "+f"(d[3])
        : "r"(a[0]), "r"(a[1]), "r"(a[2]), "r"(a[3]), "r"(b[0]), "r"(b[1]));
}
__device__ __forceinline__ void ldsm_x4(uint32_t* r, uint32_t addr) {
    asm volatile("ldmatrix.sync.aligned.m8n8.x4.shared.b16 {%0,%1,%2,%3}, [%4];"
        : "=r"(r[0]), "=r"(r[1]), "=r"(r[2]), "=r"(r[3]) : "r"(addr));
}
__device__ __forceinline__ void ldsm_x2(uint32_t* r, uint32_t addr) {
    asm volatile("ldmatrix.sync.aligned.m8n8.x2.shared.b16 {%0,%1}, [%2];"
        : "=r"(r[0]), "=r"(r[1]) : "r"(addr));
}

// ---------------- fp16-input multi-problem GEMM ----------------
// C = epi( alpha * A[M,K] * B[N,K]^T ); BM=128, BN=256, BK=64 halves;
// 8 warps (2x4), warp tile 64x64; fp32 accumulate.
// epilogue modes: 0 plain, 1 col-bias, 2 row-bias, 3 exp + partial row sums,
//                 4 scale rows by 1/rowsum (rowsum = sum of 128 partials).
#define BM 128
#define BN 256
#define BKH 64
#define STAGES 3
#define LDH 72                          // halves per smem row (144B, conflict-free)
#define A_TILE_H (128 * LDH)
#define B_TILE_H (256 * LDH)
#define STAGE_H (A_TILE_H + B_TILE_H)
#define GSMEM (STAGES * STAGE_H * 2 + 512)   // +512B rowinv -> still 1 CTA/SM

struct Prob {
    const __half* A;
    const __half* B;
    const float* bias;
    void* C;
    float* aux;      // mode 3: partials out [M][128]; mode 4: partials in
    int M, N, K;
    int tx;          // tiles in N direction
    int mode;
    float alpha;
};
struct MultiP {
    Prob p[6];
    int start[7];
};

template <typename OutT>
__global__ __launch_bounds__(256, 1)
void gemm_multi(MultiP mu)
{
    extern __shared__ __half sm[];
    int j = 0;
    const int bid = blockIdx.x;
    while (bid >= mu.start[j + 1]) j++;
    const Prob pr = mu.p[j];
    const int t = bid - mu.start[j];
    const __half* __restrict__ A = pr.A;
    const __half* __restrict__ B = pr.B;
    OutT* __restrict__ C = (OutT*)pr.C;
    const int N = pr.N;
    const int K = pr.K;
    const float alpha = pr.alpha;
    const long cRow = (long)(t / pr.tx) * BM;
    const long cCol = (long)(t % pr.tx) * BN;

    const int tid = threadIdx.x;
    const int lane = tid & 31;
    const int wid = tid >> 5;
    const int wm = (wid >> 2) * 64;
    const int wn = (wid & 3) * 64;
    const int iters = K / BKH;

    const __half* Abase = A + cRow * (long)K;
    const __half* Bbase = B + cCol * (long)K;
    float* rowinv = (float*)(sm + STAGES * STAGE_H);

    auto load_stage = [&](int jj, int s) {
        const __half* Ag = Abase + (long)jj * BKH;
        const __half* Bg = Bbase + (long)jj * BKH;
        __half* Ast = sm + s * STAGE_H;
        __half* Bst = Ast + A_TILE_H;
#pragma unroll
        for (int n = 0; n < 4; n++) {
            int c = tid + n * 256;
            int row = c >> 3, ci = c & 7;
            cp16(Ast + row * LDH + ci * 8, Ag + (long)row * K + ci * 8);
        }
#pragma unroll
        for (int n = 0; n < 8; n++) {
            int c = tid + n * 256;
            int row = c >> 3, ci = c & 7;
            cp16(Bst + row * LDH + ci * 8, Bg + (long)row * K + ci * 8);
        }
        asm volatile("cp.async.commit_group;" ::: "memory");
    };

    float acc[4][8][4];
#pragma unroll
    for (int mi = 0; mi < 4; mi++)
#pragma unroll
        for (int ni = 0; ni < 8; ni++)
#pragma unroll
            for (int r = 0; r < 4; r++) acc[mi][ni][r] = 0.f;

    const uint32_t smb = smem_u32(sm);
    const uint32_t a_off = ((wm + (lane & 15)) * LDH + (lane >> 4) * 8) * 2;
    const uint32_t b_off = ((wn + (lane & 7)) * LDH + ((lane >> 3) & 1) * 8) * 2;

#pragma unroll
    for (int jj = 0; jj < STAGES - 1; jj++) load_stage(jj, jj);

    // PV mode: reduce per-row partial sums into smem while loads fly
    if (pr.mode == 4) {
        if (tid < BM) {
            const float* pp = pr.aux + (cRow + tid) * 128;
            float s = 0.f;
#pragma unroll 16
            for (int q = 0; q < 128; q++) s += pp[q];
            rowinv[tid] = 1.f / s;
        }
        __syncthreads();
    }

    for (int i = 0; i < iters; i++) {
        if (i == iters - 1)
            asm volatile("cp.async.wait_group 0;" ::: "memory");
        else
            asm volatile("cp.async.wait_group 1;" ::: "memory");
        __syncthreads();

        const int jn = i + STAGES - 1;
        if (jn < iters) load_stage(jn, jn % STAGES);

        const uint32_t Au_b = smb + (uint32_t)((i % STAGES) * STAGE_H) * 2 + a_off;
        const uint32_t Bu_b = smb + (uint32_t)((i % STAGES) * STAGE_H + A_TILE_H) * 2 + b_off;

#pragma unroll
        for (int ks = 0; ks < 4; ks++) {
            const uint32_t kb = ks * 32;
            uint32_t a[4][4];
#pragma unroll
            for (int mi = 0; mi < 4; mi++)
                ldsm_x4(a[mi], Au_b + mi * (16 * LDH * 2) + kb);
            uint32_t b[8][2];
#pragma unroll
            for (int ni = 0; ni < 8; ni++)
                ldsm_x2(b[ni], Bu_b + ni * (8 * LDH * 2) + kb);
#pragma unroll
            for (int mi = 0; mi < 4; mi++)
#pragma unroll
                for (int ni = 0; ni < 8; ni++)
                    mma_f16(acc[mi][ni], a[mi], b[ni]);
        }
    }

    // ---------------- epilogue ----------------
    if (pr.mode == 3) {
        // u = exp(alpha*s); write fp16; deterministic partial row sums
#pragma unroll
        for (int mi = 0; mi < 4; mi++) {
            const long rg = cRow + wm + mi * 16 + (lane >> 2);
            float s0 = 0.f, s1 = 0.f;
#pragma unroll
            for (int ni = 0; ni < 8; ni++) {
                const long cg = cCol + wn + ni * 8 + (lane & 3) * 2;
                float v0 = __expf(alpha * acc[mi][ni][0]);
                float v1 = __expf(alpha * acc[mi][ni][1]);
                float v2 = __expf(alpha * acc[mi][ni][2]);
                float v3 = __expf(alpha * acc[mi][ni][3]);
                s0 += v0 + v1;
                s1 += v2 + v3;
                *(__half2*)&C[rg * (long)N + cg] = __floats2half2_rn(v0, v1);
                *(__half2*)&C[(rg + 8) * (long)N + cg] = __floats2half2_rn(v2, v3);
            }
            // reduce across the 4 lanes sharing a row (lane&3 = col subgroup)
            s0 += __shfl_xor_sync(0xFFFFFFFF, s0, 1);
            s0 += __shfl_xor_sync(0xFFFFFFFF, s0, 2);
            s1 += __shfl_xor_sync(0xFFFFFFFF, s1, 1);
            s1 += __shfl_xor_sync(0xFFFFFFFF, s1, 2);
            if ((lane & 3) == 0) {
                const int pcol = (int)(cCol / BN) * 4 + (wn >> 6);
                pr.aux[rg * 128 + pcol] = s0;
                pr.aux[(rg + 8) * 128 + pcol] = s1;
            }
        }
    } else {
        const float* __restrict__ bias = pr.bias;
#pragma unroll
        for (int mi = 0; mi < 4; mi++) {
            const long rg = cRow + wm + mi * 16 + (lane >> 2);
            float rb0 = 0.f, rb1 = 0.f;
            if (pr.mode == 2) { rb0 = __ldg(&bias[rg]); rb1 = __ldg(&bias[rg + 8]); }
            float sc0 = 1.f, sc1 = 1.f;
            if (pr.mode == 4) {
                sc0 = rowinv[wm + mi * 16 + (lane >> 2)];
                sc1 = rowinv[wm + mi * 16 + (lane >> 2) + 8];
            }
#pragma unroll
            for (int ni = 0; ni < 8; ni++) {
                const long cg = cCol + wn + ni * 8 + (lane & 3) * 2;
                float v0 = alpha * acc[mi][ni][0];
                float v1 = alpha * acc[mi][ni][1];
                float v2 = alpha * acc[mi][ni][2];
                float v3 = alpha * acc[mi][ni][3];
                if (pr.mode == 1) {
                    float cb0 = __ldg(&bias[cg]), cb1 = __ldg(&bias[cg + 1]);
                    v0 += cb0; v1 += cb1; v2 += cb0; v3 += cb1;
                } else if (pr.mode == 2) {
                    v0 += rb0; v1 += rb0; v2 += rb1; v3 += rb1;
                } else if (pr.mode == 4) {
                    v0 *= sc0; v1 *= sc0; v2 *= sc1; v3 *= sc1;
                }
                if constexpr (sizeof(OutT) == 2) {
                    *(__half2*)&C[rg * (long)N + cg] = __floats2half2_rn(v0, v1);
                    *(__half2*)&C[(rg + 8) * (long)N + cg] = __floats2half2_rn(v2, v3);
                } else {
                    float2 lo; lo.x = v0; lo.y = v1;
                    float2 hi; hi.x = v2; hi.y = v3;
                    *(float2*)&C[rg * (long)N + cg] = lo;
                    *(float2*)&C[(rg + 8) * (long)N + cg] = hi;
                }
            }
        }
    }
}

// ---------------- fp32 -> fp16 conversion ----------------
__global__ void f2h_kernel(const float4* __restrict__ in, __half2* __restrict__ out, int n4) {
    int i = blockIdx.x * blockDim.x + threadIdx.x;
    int st = gridDim.x * blockDim.x;
    for (; i < n4; i += st) {
        float4 v = in[i];
        out[2 * i + 0] = __floats2half2_rn(v.x, v.y);
        out[2 * i + 1] = __floats2half2_rn(v.z, v.w);
    }
}

struct WPtrs { const float4* in[7]; __half2* out[7]; };
__global__ void f2h_w_kernel(WPtrs wp, int n4) {
    const float4* in = wp.in[blockIdx.y];
    __half2* out = wp.out[blockIdx.y];
    int i = blockIdx.x * blockDim.x + threadIdx.x;
    int st = gridDim.x * blockDim.x;
    for (; i < n4; i += st) {
        float4 v = in[i];
        out[2 * i + 0] = __floats2half2_rn(v.x, v.y);
        out[2 * i + 1] = __floats2half2_rn(v.z, v.w);
    }
}

// ---------------- cpair = f1*f2 ; LayerNorm ; PReLU ; fp16 out ----------------
__global__ __launch_bounds__(256) void gate_ln_kernel(
    const __half* __restrict__ f1, const __half* __restrict__ f2,
    const float* __restrict__ lnw, const float* __restrict__ lnb,
    const float* __restrict__ prelu_a, __half* __restrict__ x)
{
    const int row = blockIdx.x;
    const int tid = threadIdx.x;
    const uint2 ua = ((const uint2*)(f1 + (long)row * LAT))[tid];
    const uint2 ub = ((const uint2*)(f2 + (long)row * LAT))[tid];
    float2 a01 = __half22float2(*(const __half2*)&ua.x);
    float2 a23 = __half22float2(*(const __half2*)&ua.y);
    float2 b01 = __half22float2(*(const __half2*)&ub.x);
    float2 b23 = __half22float2(*(const __half2*)&ub.y);
    float cx = a01.x * b01.x, cy = a01.y * b01.y;
    float cz = a23.x * b23.x, cw = a23.y * b23.y;

    __shared__ float red[256];
    red[tid] = cx + cy + cz + cw;
    __syncthreads();
    for (int s = 128; s > 0; s >>= 1) {
        if (tid < s) red[tid] += red[tid + s];
        __syncthreads();
    }
    const float mu = red[0] * (1.f / LAT);
    __syncthreads();
    float dx = cx - mu, dy = cy - mu, dz = cz - mu, dw = cw - mu;
    red[tid] = dx * dx + dy * dy + dz * dz + dw * dw;
    __syncthreads();
    for (int s = 128; s > 0; s >>= 1) {
        if (tid < s) red[tid] += red[tid + s];
        __syncthreads();
    }
    const float rstd = rsqrtf(red[0] * (1.f / LAT) + 1e-5f);
    const float slope = prelu_a[0];
    const float4 w = ((const float4*)lnw)[tid];
    const float4 bb = ((const float4*)lnb)[tid];
    float ox = dx * rstd * w.x + bb.x;
    float oy = dy * rstd * w.y + bb.y;
    float oz = dz * rstd * w.z + bb.z;
    float ow = dw * rstd * w.w + bb.w;
    ox = ox >= 0.f ? ox : slope * ox;
    oy = oy >= 0.f ? oy : slope * oy;
    oz = oz >= 0.f ? oz : slope * oz;
    ow = ow >= 0.f ? ow : slope * ow;
    uint2 o;
    *(__half2*)&o.x = __floats2half2_rn(ox, oy);
    *(__half2*)&o.y = __floats2half2_rn(oz, ow);
    ((uint2*)(x + (long)row * LAT))[tid] = o;
}

// ---------------- launch ----------------
static inline Prob mkprob(const __half* A, const __half* B, const float* bias, void* C,
                          float* aux, int M, int N, int K, int mode, float alpha) {
    Prob p; p.A = A; p.B = B; p.bias = bias; p.C = C; p.aux = aux;
    p.M = M; p.N = N; p.K = K; p.tx = N / BN; p.mode = mode; p.alpha = alpha;
    return p;
}

extern "C" void kernel_launch(void* const* d_in, const int* in_sizes, int n_in,
                              void* d_out, int out_size)
{
    const float* feat = (const float*)d_in[0];
    const float* bank = (const float*)d_in[1];
    const float* Wc1 = (const float*)d_in[2];  const float* bc1 = (const float*)d_in[3];
    const float* Wc2 = (const float*)d_in[4];  const float* bc2 = (const float*)d_in[5];
    const float* Wc3 = (const float*)d_in[6];  const float* bc3 = (const float*)d_in[7];
    const float* Wd1 = (const float*)d_in[8];  const float* bd1 = (const float*)d_in[9];
    const float* Wd2 = (const float*)d_in[10]; const float* bd2 = (const float*)d_in[11];
    const float* Wd3 = (const float*)d_in[12]; const float* bd3 = (const float*)d_in[13];
    const float* lnw = (const float*)d_in[14]; const float* lnb = (const float*)d_in[15];
    const float* pra = (const float*)d_in[16];
    const float* Wffn = (const float*)d_in[17]; const float* bffn = (const float*)d_in[18];
    float* out = (float*)d_out;

    __half *hfeat, *hbank, *hw, *q1, *q2, *k1, *k2, *v1t, *v2t, *p1, *p2, *f1, *f2, *x;
    float *ps1, *ps2;
    cudaGetSymbolAddress((void**)&hfeat, g_hfeat);
    cudaGetSymbolAddress((void**)&hbank, g_hbank);
    cudaGetSymbolAddress((void**)&hw, g_hw);
    cudaGetSymbolAddress((void**)&q1, g_q1);
    cudaGetSymbolAddress((void**)&q2, g_q2);
    cudaGetSymbolAddress((void**)&k1, g_k1);
    cudaGetSymbolAddress((void**)&k2, g_k2);
    cudaGetSymbolAddress((void**)&v1t, g_v1t);
    cudaGetSymbolAddress((void**)&v2t, g_v2t);
    cudaGetSymbolAddress((void**)&p1, g_p1);
    cudaGetSymbolAddress((void**)&p2, g_p2);
    cudaGetSymbolAddress((void**)&ps1, g_ps1);
    cudaGetSymbolAddress((void**)&ps2, g_ps2);
    cudaGetSymbolAddress((void**)&f1, g_f1);
    cudaGetSymbolAddress((void**)&f2, g_f2);
    cudaGetSymbolAddress((void**)&x, g_x);
    const long WSZ = (long)LAT * DIMIN;
    __half* hWc1 = hw + 0 * WSZ;  __half* hWc2 = hw + 1 * WSZ;  __half* hWc3 = hw + 2 * WSZ;
    __half* hWd1 = hw + 3 * WSZ;  __half* hWd2 = hw + 4 * WSZ;  __half* hWd3 = hw + 5 * WSZ;
    __half* hWffn = hw + 6 * WSZ;

    cudaFuncSetAttribute(gemm_multi<__half>, cudaFuncAttributeMaxDynamicSharedMemorySize, GSMEM);
    cudaFuncSetAttribute(gemm_multi<float>,  cudaFuncAttributeMaxDynamicSharedMemorySize, GSMEM);

    // convert all GEMM inputs to fp16
    f2h_kernel<<<2048, 256>>>((const float4*)feat, (__half2*)hfeat, (int)((long)NROIS * QDIM_ / 4));
    f2h_kernel<<<4096, 256>>>((const float4*)bank, (__half2*)hbank, (int)((long)NBANK * DIMIN / 4));
    {
        WPtrs wp;
        wp.in[0] = (const float4*)Wc1;  wp.out[0] = (__half2*)hWc1;
        wp.in[1] = (const float4*)Wc2;  wp.out[1] = (__half2*)hWc2;
        wp.in[2] = (const float4*)Wc3;  wp.out[2] = (__half2*)hWc3;
        wp.in[3] = (const float4*)Wd1;  wp.out[3] = (__half2*)hWd1;
        wp.in[4] = (const float4*)Wd2;  wp.out[4] = (__half2*)hWd2;
        wp.in[5] = (const float4*)Wd3;  wp.out[5] = (__half2*)hWd3;
        wp.in[6] = (const float4*)Wffn; wp.out[6] = (__half2*)hWffn;
        f2h_w_kernel<<<dim3(512, 7), 256>>>(wp, (int)(WSZ / 4));
    }

    const dim3 blk(256);
    const float inv_sqrt = 0.03125f;  // 1/sqrt(1024)

    // Phase B: all 6 projections in one launch
    {
        MultiP mu;
        mu.p[0] = mkprob(hfeat, hWc1, bc1, q1, nullptr, NROIS, LAT, QDIM_, 1, 1.f);   // 128 tiles
        mu.p[1] = mkprob(hfeat, hWd1, bd1, q2, nullptr, NROIS, LAT, QDIM_, 1, 1.f);   // 128
        mu.p[2] = mkprob(hbank, hWc2, bc2, k1, nullptr, NBANK, LAT, DIMIN, 1, 1.f);   // 256
        mu.p[3] = mkprob(hbank, hWd2, bd2, k2, nullptr, NBANK, LAT, DIMIN, 1, 1.f);   // 256
        mu.p[4] = mkprob(hWc3, hbank, bc3, v1t, nullptr, LAT, NBANK, DIMIN, 2, 1.f);  // 256
        mu.p[5] = mkprob(hWd3, hbank, bd3, v2t, nullptr, LAT, NBANK, DIMIN, 2, 1.f);  // 256
        int st[7] = {0, 128, 256, 512, 768, 1024, 1280};
        for (int i = 0; i < 7; i++) mu.start[i] = st[i];
        gemm_multi<__half><<<1280, blk, GSMEM>>>(mu);
    }
    // Phase C: QK1 with fused exp + partial sums
    {
        MultiP mu;
        mu.p[0] = mkprob(q1, k1, nullptr, p1, ps1, NROIS, NBANK, LAT, 3, inv_sqrt);  // 1024 tiles
        mu.start[0] = 0;
        for (int i = 1; i < 7; i++) mu.start[i] = 1024;
        gemm_multi<__half><<<1024, blk, GSMEM>>>(mu);
    }
    // Phase E: PV1 (rowscale, long tiles first) + QK2 (exp) in one launch
    {
        MultiP mu;
        mu.p[0] = mkprob(p1, v1t, nullptr, f1, ps1, NROIS, LAT, NBANK, 4, 1.f);      // 128 long
        mu.p[1] = mkprob(q2, k2, nullptr, p2, ps2, NROIS, NBANK, LAT, 3, inv_sqrt);  // 1024
        mu.start[0] = 0; mu.start[1] = 128;
        for (int i = 2; i < 7; i++) mu.start[i] = 1152;
        gemm_multi<__half><<<1152, blk, GSMEM>>>(mu);
    }
    // Phase G: PV2 (rowscale)
    {
        MultiP mu;
        mu.p[0] = mkprob(p2, v2t, nullptr, f2, ps2, NROIS, LAT, NBANK, 4, 1.f);  // 128 tiles
        mu.start[0] = 0;
        for (int i = 1; i < 7; i++) mu.start[i] = 128;
        gemm_multi<__half><<<128, blk, GSMEM>>>(mu);
    }
    // Phase H: gate + LayerNorm + PReLU
    gate_ln_kernel<<<NROIS, blk>>>(f1, f2, lnw, lnb, pra, x);
    // Phase I: FFN (fp32 out)
    {
        MultiP mu;
        mu.p[0] = mkprob(x, hWffn, bffn, out, nullptr, NROIS, DIMIN, LAT, 1, 1.f);  // 256 tiles
        mu.start[0] = 0;
        for (int i = 1; i < 7; i++) mu.start[i] = 256;
        gemm_multi<float><<<256, blk, GSMEM>>>(mu);
    }
}

// round 11
// speedup vs baseline: 8.0729x; 1.0285x over previous
#include <cuda_runtime.h>
#include <cuda_fp16.h>
#include <cstdint>

#define NROIS 4096
#define NBANK 8192
#define DIMIN 2048
#define QDIM_ 2048
#define LAT 1024

// ---------------- scratch (device globals: allocation-free) ----------------
__device__ __half g_hfeat[NROIS * QDIM_];
__device__ __half g_hbank[NBANK * DIMIN];
__device__ __half g_hw[7][LAT * DIMIN];   // Wc1,Wc2,Wc3,Wd1,Wd2,Wd3,Wffn
__device__ __half g_q1[NROIS * LAT];
__device__ __half g_q2[NROIS * LAT];
__device__ __half g_k1[NBANK * LAT];
__device__ __half g_k2[NBANK * LAT];
__device__ __half g_v1t[LAT * NBANK];
__device__ __half g_v2t[LAT * NBANK];
__device__ __half g_p1[(long)NROIS * NBANK];
__device__ __half g_p2[(long)NROIS * NBANK];
__device__ float g_ps1[NROIS * 128];      // per-row partial exp-sums, branch 1
__device__ float g_ps2[NROIS * 128];      // branch 2
__device__ __half g_f1[NROIS * LAT];
__device__ __half g_f2[NROIS * LAT];
__device__ __half g_x[NROIS * LAT];

// ---------------- helpers ----------------
__device__ __forceinline__ uint32_t smem_u32(const void* p) {
    uint32_t r;
    asm("{ .reg .u64 t; cvta.to.shared.u64 t, %1; cvt.u32.u64 %0, t; }" : "=r"(r) : "l"(p));
    return r;
}
__device__ __forceinline__ void cp16(const __half* smem_dst, const __half* gsrc) {
    uint32_t a = smem_u32(smem_dst);
    asm volatile("cp.async.cg.shared.global [%0], [%1], 16;" :: "r"(a), "l"(gsrc) : "memory");
}
__device__ __forceinline__ void mma_f16(float* d, const uint32_t* a, const uint32_t* b) {
    asm volatile(
        "mma.sync.aligned.m16n8k16.row.col.f32.f16.f16.f32 "
        "{%0,%1,%2,%3}, {%4,%5,%6,%7}, {%8,%9}, {%0,%1,%2,%3};"
        : "+f"(d[0]), "+f"(d[1]), "+f"(d[2]), "+f"(d[3])
        : "r"(a[0]), "r"(a[1]), "r"(a[2]), "r"(a[3]), "r"(b[0]), "r"(b[1]));
}
__device__ __forceinline__ void ldsm_x4(uint32_t* r, uint32_t addr) {
    asm volatile("ldmatrix.sync.aligned.m8n8.x4.shared.b16 {%0,%1,%2,%3}, [%4];"
        : "=r"(r[0]), "=r"(r[1]), "=r"(r[2]), "=r"(r[3]) : "r"(addr));
}

// ---------------- fp16-input multi-problem GEMM ----------------
// C = epi( alpha * A[M,K] * B[N,K]^T ); BM=128, BN=256, BK=64 halves;
// 8 warps (2x4), warp tile 64x64; fp32 accumulate.
// epilogue modes: 0 plain, 1 col-bias, 2 row-bias, 3 exp + partial row sums,
//                 4 scale rows by 1/rowsum (rowsum = sum of 128 partials).
#define BM 128
#define BN 256
#define BKH 64
#define STAGES 3
#define LDH 72                          // halves per smem row (144B, conflict-free)
#define A_TILE_H (128 * LDH)
#define B_TILE_H (256 * LDH)
#define STAGE_H (A_TILE_H + B_TILE_H)
#define GSMEM (STAGES * STAGE_H * 2 + 512)   // +512B rowinv -> still 1 CTA/SM

struct Prob {
    const __half* A;
    const __half* B;
    const float* bias;
    void* C;
    float* aux;      // mode 3: partials out [M][128]; mode 4: partials in
    int M, N, K;
    int tx;          // tiles in N direction
    int mode;
    float alpha;
};
struct MultiP {
    Prob p[6];
    int start[7];
};

template <typename OutT>
__global__ __launch_bounds__(256, 1)
void gemm_multi(MultiP mu)
{
    extern __shared__ __half sm[];
    int j = 0;
    const int bid = blockIdx.x;
    while (bid >= mu.start[j + 1]) j++;
    const Prob pr = mu.p[j];
    const int t = bid - mu.start[j];
    const __half* __restrict__ A = pr.A;
    const __half* __restrict__ B = pr.B;
    OutT* __restrict__ C = (OutT*)pr.C;
    const int N = pr.N;
    const int K = pr.K;
    const float alpha = pr.alpha;
    const long cRow = (long)(t / pr.tx) * BM;
    const long cCol = (long)(t % pr.tx) * BN;

    const int tid = threadIdx.x;
    const int lane = tid & 31;
    const int wid = tid >> 5;
    const int wm = (wid >> 2) * 64;
    const int wn = (wid & 3) * 64;
    const int iters = K / BKH;

    const __half* Abase = A + cRow * (long)K;
    const __half* Bbase = B + cCol * (long)K;
    float* rowinv = (float*)(sm + STAGES * STAGE_H);

    auto load_stage = [&](int jj, int s) {
        const __half* Ag = Abase + (long)jj * BKH;
        const __half* Bg = Bbase + (long)jj * BKH;
        __half* Ast = sm + s * STAGE_H;
        __half* Bst = Ast + A_TILE_H;
#pragma unroll
        for (int n = 0; n < 4; n++) {
            int c = tid + n * 256;
            int row = c >> 3, ci = c & 7;
            cp16(Ast + row * LDH + ci * 8, Ag + (long)row * K + ci * 8);
        }
#pragma unroll
        for (int n = 0; n < 8; n++) {
            int c = tid + n * 256;
            int row = c >> 3, ci = c & 7;
            cp16(Bst + row * LDH + ci * 8, Bg + (long)row * K + ci * 8);
        }
        asm volatile("cp.async.commit_group;" ::: "memory");
    };

    float acc[4][8][4];
#pragma unroll
    for (int mi = 0; mi < 4; mi++)
#pragma unroll
        for (int ni = 0; ni < 8; ni++)
#pragma unroll
            for (int r = 0; r < 4; r++) acc[mi][ni][r] = 0.f;

    const uint32_t smb = smem_u32(sm);
    // A x4: lanes 0-15 -> rows wm..wm+15; lanes 16-31 -> k-half 1
    const uint32_t a_off = ((wm + (lane & 15)) * LDH + (lane >> 4) * 8) * 2;
    // B x4 covering TWO n8 tiles: lanes 0-7 rows wn+r (kh0), 8-15 (kh1),
    //                             16-23 rows wn+8+r (kh0), 24-31 (kh1)
    const uint32_t b_off = ((wn + (lane & 7) + ((lane >> 4) << 3)) * LDH
                            + ((lane >> 3) & 1) * 8) * 2;

#pragma unroll
    for (int jj = 0; jj < STAGES - 1; jj++) load_stage(jj, jj);

    // PV mode: reduce per-row partial sums into smem while loads fly
    if (pr.mode == 4) {
        if (tid < BM) {
            const float* pp = pr.aux + (cRow + tid) * 128;
            float s = 0.f;
#pragma unroll 16
            for (int q = 0; q < 128; q++) s += pp[q];
            rowinv[tid] = 1.f / s;
        }
        __syncthreads();
    }

    for (int i = 0; i < iters; i++) {
        if (i == iters - 1)
            asm volatile("cp.async.wait_group 0;" ::: "memory");
        else
            asm volatile("cp.async.wait_group 1;" ::: "memory");
        __syncthreads();

        const int jn = i + STAGES - 1;
        if (jn < iters) load_stage(jn, jn % STAGES);

        const uint32_t Au_b = smb + (uint32_t)((i % STAGES) * STAGE_H) * 2 + a_off;
        const uint32_t Bu_b = smb + (uint32_t)((i % STAGES) * STAGE_H + A_TILE_H) * 2 + b_off;

#pragma unroll
        for (int ks = 0; ks < 4; ks++) {
            const uint32_t kb = ks * 32;
            uint32_t a[4][4];
#pragma unroll
            for (int mi = 0; mi < 4; mi++)
                ldsm_x4(a[mi], Au_b + mi * (16 * LDH * 2) + kb);
            uint32_t b[4][4];        // 4 pairs x (2 tiles x 2 khalf regs)
#pragma unroll
            for (int np = 0; np < 4; np++)
                ldsm_x4(b[np], Bu_b + np * (16 * LDH * 2) + kb);
#pragma unroll
            for (int mi = 0; mi < 4; mi++)
#pragma unroll
                for (int ni = 0; ni < 8; ni++)
                    mma_f16(acc[mi][ni], a[mi], &b[ni >> 1][(ni & 1) * 2]);
        }
    }

    // ---------------- epilogue ----------------
    if (pr.mode == 3) {
        // u = exp(alpha*s); write fp16; deterministic partial row sums
#pragma unroll
        for (int mi = 0; mi < 4; mi++) {
            const long rg = cRow + wm + mi * 16 + (lane >> 2);
            float s0 = 0.f, s1 = 0.f;
#pragma unroll
            for (int ni = 0; ni < 8; ni++) {
                const long cg = cCol + wn + ni * 8 + (lane & 3) * 2;
                float v0 = __expf(alpha * acc[mi][ni][0]);
                float v1 = __expf(alpha * acc[mi][ni][1]);
                float v2 = __expf(alpha * acc[mi][ni][2]);
                float v3 = __expf(alpha * acc[mi][ni][3]);
                s0 += v0 + v1;
                s1 += v2 + v3;
                *(__half2*)&C[rg * (long)N + cg] = __floats2half2_rn(v0, v1);
                *(__half2*)&C[(rg + 8) * (long)N + cg] = __floats2half2_rn(v2, v3);
            }
            s0 += __shfl_xor_sync(0xFFFFFFFF, s0, 1);
            s0 += __shfl_xor_sync(0xFFFFFFFF, s0, 2);
            s1 += __shfl_xor_sync(0xFFFFFFFF, s1, 1);
            s1 += __shfl_xor_sync(0xFFFFFFFF, s1, 2);
            if ((lane & 3) == 0) {
                const int pcol = (int)(cCol / BN) * 4 + (wn >> 6);
                pr.aux[rg * 128 + pcol] = s0;
                pr.aux[(rg + 8) * 128 + pcol] = s1;
            }
        }
    } else {
        const float* __restrict__ bias = pr.bias;
#pragma unroll
        for (int mi = 0; mi < 4; mi++) {
            const long rg = cRow + wm + mi * 16 + (lane >> 2);
            float rb0 = 0.f, rb1 = 0.f;
            if (pr.mode == 2) { rb0 = __ldg(&bias[rg]); rb1 = __ldg(&bias[rg + 8]); }
            float sc0 = 1.f, sc1 = 1.f;
            if (pr.mode == 4) {
                sc0 = rowinv[wm + mi * 16 + (lane >> 2)];
                sc1 = rowinv[wm + mi * 16 + (lane >> 2) + 8];
            }
#pragma unroll
            for (int ni = 0; ni < 8; ni++) {
                const long cg = cCol + wn + ni * 8 + (lane & 3) * 2;
                float v0 = alpha * acc[mi][ni][0];
                float v1 = alpha * acc[mi][ni][1];
                float v2 = alpha * acc[mi][ni][2];
                float v3 = alpha * acc[mi][ni][3];
                if (pr.mode == 1) {
                    float cb0 = __ldg(&bias[cg]), cb1 = __ldg(&bias[cg + 1]);
                    v0 += cb0; v1 += cb1; v2 += cb0; v3 += cb1;
                } else if (pr.mode == 2) {
                    v0 += rb0; v1 += rb0; v2 += rb1; v3 += rb1;
                } else if (pr.mode == 4) {
                    v0 *= sc0; v1 *= sc0; v2 *= sc1; v3 *= sc1;
                }
                if constexpr (sizeof(OutT) == 2) {
                    *(__half2*)&C[rg * (long)N + cg] = __floats2half2_rn(v0, v1);
                    *(__half2*)&C[(rg + 8) * (long)N + cg] = __floats2half2_rn(v2, v3);
                } else {
                    float2 lo; lo.x = v0; lo.y = v1;
                    float2 hi; hi.x = v2; hi.y = v3;
                    *(float2*)&C[rg * (long)N + cg] = lo;
                    *(float2*)&C[(rg + 8) * (long)N + cg] = hi;
                }
            }
        }
    }
}

// ---------------- fp32 -> fp16 conversion: 9 segments in one launch ----------------
struct CvtP { const float4* in[9]; __half2* out[9]; int n4[9]; };
__global__ void f2h_all_kernel(CvtP cp) {
    const float4* in = cp.in[blockIdx.y];
    __half2* out = cp.out[blockIdx.y];
    const int n4 = cp.n4[blockIdx.y];
    int i = blockIdx.x * blockDim.x + threadIdx.x;
    int st = gridDim.x * blockDim.x;
    for (; i < n4; i += st) {
        float4 v = in[i];
        out[2 * i + 0] = __floats2half2_rn(v.x, v.y);
        out[2 * i + 1] = __floats2half2_rn(v.z, v.w);
    }
}

// ---------------- cpair = f1*f2 ; LayerNorm ; PReLU ; fp16 out ----------------
__global__ __launch_bounds__(256) void gate_ln_kernel(
    const __half* __restrict__ f1, const __half* __restrict__ f2,
    const float* __restrict__ lnw, const float* __restrict__ lnb,
    const float* __restrict__ prelu_a, __half* __restrict__ x)
{
    const int row = blockIdx.x;
    const int tid = threadIdx.x;
    const uint2 ua = ((const uint2*)(f1 + (long)row * LAT))[tid];
    const uint2 ub = ((const uint2*)(f2 + (long)row * LAT))[tid];
    float2 a01 = __half22float2(*(const __half2*)&ua.x);
    float2 a23 = __half22float2(*(const __half2*)&ua.y);
    float2 b01 = __half22float2(*(const __half2*)&ub.x);
    float2 b23 = __half22float2(*(const __half2*)&ub.y);
    float cx = a01.x * b01.x, cy = a01.y * b01.y;
    float cz = a23.x * b23.x, cw = a23.y * b23.y;

    __shared__ float red[256];
    red[tid] = cx + cy + cz + cw;
    __syncthreads();
    for (int s = 128; s > 0; s >>= 1) {
        if (tid < s) red[tid] += red[tid + s];
        __syncthreads();
    }
    const float mu = red[0] * (1.f / LAT);
    __syncthreads();
    float dx = cx - mu, dy = cy - mu, dz = cz - mu, dw = cw - mu;
    red[tid] = dx * dx + dy * dy + dz * dz + dw * dw;
    __syncthreads();
    for (int s = 128; s > 0; s >>= 1) {
        if (tid < s) red[tid] += red[tid + s];
        __syncthreads();
    }
    const float rstd = rsqrtf(red[0] * (1.f / LAT) + 1e-5f);
    const float slope = prelu_a[0];
    const float4 w = ((const float4*)lnw)[tid];
    const float4 bb = ((const float4*)lnb)[tid];
    float ox = dx * rstd * w.x + bb.x;
    float oy = dy * rstd * w.y + bb.y;
    float oz = dz * rstd * w.z + bb.z;
    float ow = dw * rstd * w.w + bb.w;
    ox = ox >= 0.f ? ox : slope * ox;
    oy = oy >= 0.f ? oy : slope * oy;
    oz = oz >= 0.f ? oz : slope * oz;
    ow = ow >= 0.f ? ow : slope * ow;
    uint2 o;
    *(__half2*)&o.x = __floats2half2_rn(ox, oy);
    *(__half2*)&o.y = __floats2half2_rn(oz, ow);
    ((uint2*)(x + (long)row * LAT))[tid] = o;
}

// ---------------- launch ----------------
static inline Prob mkprob(const __half* A, const __half* B, const float* bias, void* C,
                          float* aux, int M, int N, int K, int mode, float alpha) {
    Prob p; p.A = A; p.B = B; p.bias = bias; p.C = C; p.aux = aux;
    p.M = M; p.N = N; p.K = K; p.tx = N / BN; p.mode = mode; p.alpha = alpha;
    return p;
}

extern "C" void kernel_launch(void* const* d_in, const int* in_sizes, int n_in,
                              void* d_out, int out_size)
{
    const float* feat = (const float*)d_in[0];
    const float* bank = (const float*)d_in[1];
    const float* Wc1 = (const float*)d_in[2];  const float* bc1 = (const float*)d_in[3];
    const float* Wc2 = (const float*)d_in[4];  const float* bc2 = (const float*)d_in[5];
    const float* Wc3 = (const float*)d_in[6];  const float* bc3 = (const float*)d_in[7];
    const float* Wd1 = (const float*)d_in[8];  const float* bd1 = (const float*)d_in[9];
    const float* Wd2 = (const float*)d_in[10]; const float* bd2 = (const float*)d_in[11];
    const float* Wd3 = (const float*)d_in[12]; const float* bd3 = (const float*)d_in[13];
    const float* lnw = (const float*)d_in[14]; const float* lnb = (const float*)d_in[15];
    const float* pra = (const float*)d_in[16];
    const float* Wffn = (const float*)d_in[17]; const float* bffn = (const float*)d_in[18];
    float* out = (float*)d_out;

    __half *hfeat, *hbank, *hw, *q1, *q2, *k1, *k2, *v1t, *v2t, *p1, *p2, *f1, *f2, *x;
    float *ps1, *ps2;
    cudaGetSymbolAddress((void**)&hfeat, g_hfeat);
    cudaGetSymbolAddress((void**)&hbank, g_hbank);
    cudaGetSymbolAddress((void**)&hw, g_hw);
    cudaGetSymbolAddress((void**)&q1, g_q1);
    cudaGetSymbolAddress((void**)&q2, g_q2);
    cudaGetSymbolAddress((void**)&k1, g_k1);
    cudaGetSymbolAddress((void**)&k2, g_k2);
    cudaGetSymbolAddress((void**)&v1t, g_v1t);
    cudaGetSymbolAddress((void**)&v2t, g_v2t);
    cudaGetSymbolAddress((void**)&p1, g_p1);
    cudaGetSymbolAddress((void**)&p2, g_p2);
    cudaGetSymbolAddress((void**)&ps1, g_ps1);
    cudaGetSymbolAddress((void**)&ps2, g_ps2);
    cudaGetSymbolAddress((void**)&f1, g_f1);
    cudaGetSymbolAddress((void**)&f2, g_f2);
    cudaGetSymbolAddress((void**)&x, g_x);
    const long WSZ = (long)LAT * DIMIN;
    __half* hWc1 = hw + 0 * WSZ;  __half* hWc2 = hw + 1 * WSZ;  __half* hWc3 = hw + 2 * WSZ;
    __half* hWd1 = hw + 3 * WSZ;  __half* hWd2 = hw + 4 * WSZ;  __half* hWd3 = hw + 5 * WSZ;
    __half* hWffn = hw + 6 * WSZ;

    cudaFuncSetAttribute(gemm_multi<__half>, cudaFuncAttributeMaxDynamicSharedMemorySize, GSMEM);
    cudaFuncSetAttribute(gemm_multi<float>,  cudaFuncAttributeMaxDynamicSharedMemorySize, GSMEM);

    // convert all GEMM inputs to fp16 in one launch (9 segments)
    {
        CvtP cp;
        cp.in[0] = (const float4*)feat; cp.out[0] = (__half2*)hfeat; cp.n4[0] = (int)((long)NROIS * QDIM_ / 4);
        cp.in[1] = (const float4*)bank; cp.out[1] = (__half2*)hbank; cp.n4[1] = (int)((long)NBANK * DIMIN / 4);
        cp.in[2] = (const float4*)Wc1;  cp.out[2] = (__half2*)hWc1;  cp.n4[2] = (int)(WSZ / 4);
        cp.in[3] = (const float4*)Wc2;  cp.out[3] = (__half2*)hWc2;  cp.n4[3] = (int)(WSZ / 4);
        cp.in[4] = (const float4*)Wc3;  cp.out[4] = (__half2*)hWc3;  cp.n4[4] = (int)(WSZ / 4);
        cp.in[5] = (const float4*)Wd1;  cp.out[5] = (__half2*)hWd1;  cp.n4[5] = (int)(WSZ / 4);
        cp.in[6] = (const float4*)Wd2;  cp.out[6] = (__half2*)hWd2;  cp.n4[6] = (int)(WSZ / 4);
        cp.in[7] = (const float4*)Wd3;  cp.out[7] = (__half2*)hWd3;  cp.n4[7] = (int)(WSZ / 4);
        cp.in[8] = (const float4*)Wffn; cp.out[8] = (__half2*)hWffn; cp.n4[8] = (int)(WSZ / 4);
        f2h_all_kernel<<<dim3(480, 9), 256>>>(cp);
    }

    const dim3 blk(256);
    const float inv_sqrt = 0.03125f;  // 1/sqrt(1024)

    // Phase B: all 6 projections in one launch
    {
        MultiP mu;
        mu.p[0] = mkprob(hfeat, hWc1, bc1, q1, nullptr, NROIS, LAT, QDIM_, 1, 1.f);   // 128 tiles
        mu.p[1] = mkprob(hfeat, hWd1, bd1, q2, nullptr, NROIS, LAT, QDIM_, 1, 1.f);   // 128
        mu.p[2] = mkprob(hbank, hWc2, bc2, k1, nullptr, NBANK, LAT, DIMIN, 1, 1.f);   // 256
        mu.p[3] = mkprob(hbank, hWd2, bd2, k2, nullptr, NBANK, LAT, DIMIN, 1, 1.f);   // 256
        mu.p[4] = mkprob(hWc3, hbank, bc3, v1t, nullptr, LAT, NBANK, DIMIN, 2, 1.f);  // 256
        mu.p[5] = mkprob(hWd3, hbank, bd3, v2t, nullptr, LAT, NBANK, DIMIN, 2, 1.f);  // 256
        int st[7] = {0, 128, 256, 512, 768, 1024, 1280};
        for (int i = 0; i < 7; i++) mu.start[i] = st[i];
        gemm_multi<__half><<<1280, blk, GSMEM>>>(mu);
    }
    // Phase C: QK1 with fused exp + partial sums
    {
        MultiP mu;
        mu.p[0] = mkprob(q1, k1, nullptr, p1, ps1, NROIS, NBANK, LAT, 3, inv_sqrt);  // 1024 tiles
        mu.start[0] = 0;
        for (int i = 1; i < 7; i++) mu.start[i] = 1024;
        gemm_multi<__half><<<1024, blk, GSMEM>>>(mu);
    }
    // Phase E: PV1 (rowscale, long tiles first) + QK2 (exp) in one launch
    {
        MultiP mu;
        mu.p[0] = mkprob(p1, v1t, nullptr, f1, ps1, NROIS, LAT, NBANK, 4, 1.f);      // 128 long
        mu.p[1] = mkprob(q2, k2, nullptr, p2, ps2, NROIS, NBANK, LAT, 3, inv_sqrt);  // 1024
        mu.start[0] = 0; mu.start[1] = 128;
        for (int i = 2; i < 7; i++) mu.start[i] = 1152;
        gemm_multi<__half><<<1152, blk, GSMEM>>>(mu);
    }
    // Phase G: PV2 (rowscale)
    {
        MultiP mu;
        mu.p[0] = mkprob(p2, v2t, nullptr, f2, ps2, NROIS, LAT, NBANK, 4, 1.f);  // 128 tiles
        mu.start[0] = 0;
        for (int i = 1; i < 7; i++) mu.start[i] = 128;
        gemm_multi<__half><<<128, blk, GSMEM>>>(mu);
    }
    // Phase H: gate + LayerNorm + PReLU
    gate_ln_kernel<<<NROIS, blk>>>(f1, f2, lnw, lnb, pra, x);
    // Phase I: FFN (fp32 out)
    {
        MultiP mu;
        mu.p[0] = mkprob(x, hWffn, bffn, out, nullptr, NROIS, DIMIN, LAT, 1, 1.f);  // 256 tiles
        mu.start[0] = 0;
        for (int i = 1; i < 7; i++) mu.start[i] = 256;
        gemm_multi<float><<<256, blk, GSMEM>>>(mu);
    }
}